// round 7
// baseline (speedup 1.0000x reference)
#include <cuda_runtime.h>
#include <cuda_fp16.h>
#include <cstdint>

#define SEQ 4096
#define DM 1024
#define MTOT 32768

// ---- scratch (device globals: sanctioned no-alloc workaround) ----
__device__ __half g_Q[(size_t)MTOT * DM];
__device__ __half g_K[(size_t)MTOT * DM];
__device__ __half g_V[(size_t)MTOT * DM];
__device__ __half g_MID[(size_t)MTOT * DM];
__device__ __half g_X[(size_t)MTOT * DM];         // fp16 x
__device__ __half g_W[(size_t)3 * DM * DM];       // fp16 [Wq;Wk;Wv]
__device__ __half g_Wo[(size_t)DM * DM];          // fp16 Wo

// ---------------------------------------------------------------------------
// helpers
// ---------------------------------------------------------------------------
__device__ __forceinline__ uint32_t smem_u32(const void* p) {
    uint32_t a;
    asm("{ .reg .u64 t; cvta.to.shared.u64 t, %1; cvt.u32.u64 %0, t; }" : "=r"(a) : "l"(p));
    return a;
}
__device__ __forceinline__ void cpasync16(uint32_t dst, const void* src) {
    asm volatile("cp.async.cg.shared.global [%0], [%1], 16;" :: "r"(dst), "l"(src) : "memory");
}
__device__ __forceinline__ void ldsm4(uint32_t* r, uint32_t addr) {
    asm volatile("ldmatrix.sync.aligned.m8n8.x4.shared.b16 {%0,%1,%2,%3}, [%4];"
                 : "=r"(r[0]), "=r"(r[1]), "=r"(r[2]), "=r"(r[3]) : "r"(addr));
}
__device__ __forceinline__ void mma_f16(float* c, const uint32_t* a, const uint32_t* b) {
    asm volatile(
        "mma.sync.aligned.m16n8k16.row.col.f32.f16.f16.f32 "
        "{%0,%1,%2,%3}, {%4,%5,%6,%7}, {%8,%9}, {%0,%1,%2,%3};\n"
        : "+f"(c[0]), "+f"(c[1]), "+f"(c[2]), "+f"(c[3])
        : "r"(a[0]), "r"(a[1]), "r"(a[2]), "r"(a[3]), "r"(b[0]), "r"(b[1]));
}

// ---------------------------------------------------------------------------
// fp32 -> fp16 convert (8 elements / thread)
// ---------------------------------------------------------------------------
__global__ void __launch_bounds__(256) cvt_h(const float4* __restrict__ src,
                                             uint4* __restrict__ dst, int n8) {
    int i = blockIdx.x * 256 + threadIdx.x;
    if (i < n8) {
        float4 a = src[2 * i], b = src[2 * i + 1];
        uint4 o;
        *(__half2*)&o.x = __floats2half2_rn(a.x, a.y);
        *(__half2*)&o.y = __floats2half2_rn(a.z, a.w);
        *(__half2*)&o.z = __floats2half2_rn(b.x, b.y);
        *(__half2*)&o.w = __floats2half2_rn(b.z, b.w);
        dst[i] = o;
    }
}

// ---------------------------------------------------------------------------
// fp16 GEMM: C[m,n] = sum_k A[m,k]*B[n,k]. Tile 128(M)x256(N), BK=64 halves
// (128B rows, XOR-16B swizzle: conflict-free cp.async stores + ldmatrix).
// 256 threads, warp grid 2(m) x 4(n), warp tile 64x64, accum 128 regs.
// 3-stage cp.async pipeline, 144KB smem, 1 CTA/SM.
// MODE 0: A=g_X, B=g_W (3072 rows), C -> g_Q/g_K/g_V (half). grid (12, 256)
// MODE 1: A=g_MID, B=g_Wo, C = out fp32 + bias.              grid (4, 256)
// ---------------------------------------------------------------------------
#define A_BYTES 16384                      // 128 rows * 128B
#define B_BYTES 32768                      // 256 rows * 128B
#define STAGE_BYTES (A_BYTES + B_BYTES)    // 49152
#define NST 3
#define GSMEM (NST * STAGE_BYTES)          // 147456

template <int MODE>
__global__ void __launch_bounds__(256, 1) gemm_h(const float* __restrict__ bias,
                                                 float* __restrict__ Cout) {
    extern __shared__ uint8_t sm_raw[];
    const uint32_t sb = smem_u32(sm_raw);
    const int tid = threadIdx.x;
    const int lane = tid & 31;
    const int wid = tid >> 5;
    const int wm = wid >> 2;         // 0..1 (m, 64 rows)
    const int wn = wid & 3;          // 0..3 (n, 64 cols)

    const int m0 = blockIdx.y * 128;
    const int n0 = blockIdx.x * 256;
    const __half* A = (MODE == 0) ? g_X : g_MID;
    const __half* B = (MODE == 0) ? g_W : g_Wo;
    const __half* Ag = A + (size_t)m0 * DM;
    const __half* Bg = B + (size_t)n0 * DM;

    // cp.async: A 1024 chunks (4/thread), B 2048 chunks (8/thread), 16B each
    int sArow[4], sAsw[4];
#pragma unroll
    for (int i = 0; i < 4; i++) {
        int id = tid + i * 256;
        int r = id >> 3, c = id & 7;
        sArow[i] = r;
        sAsw[i] = r * 128 + ((c ^ (r & 7)) << 4);
    }
    int sBrow[8], sBsw[8];
#pragma unroll
    for (int i = 0; i < 8; i++) {
        int id = tid + i * 256;
        int r = id >> 3, c = id & 7;
        sBrow[i] = r;
        sBsw[i] = r * 128 + ((c ^ (r & 7)) << 4);
    }
    const int scol8 = (tid & 7) * 8;

    // ldmatrix bases
    uint32_t aOff[4]; int aSw[4];
    const int aHi = lane >> 4;
#pragma unroll
    for (int mt = 0; mt < 4; mt++) {
        int r = wm * 64 + mt * 16 + (lane & 15);
        aOff[mt] = r * 128;
        aSw[mt] = r & 7;
    }
    uint32_t bOff[4]; int bSw[4];
    const int bHi = (lane >> 3) & 1;
#pragma unroll
    for (int np = 0; np < 4; np++) {
        int r = wn * 64 + np * 16 + ((lane >> 4) << 3) + (lane & 7);
        bOff[np] = A_BYTES + r * 128;
        bSw[np] = r & 7;
    }

    float acc[4][8][4];
#pragma unroll
    for (int mt = 0; mt < 4; mt++)
#pragma unroll
        for (int nt = 0; nt < 8; nt++)
#pragma unroll
            for (int i = 0; i < 4; i++) acc[mt][nt][i] = 0.f;

    // ---- prologue: stages 0,1 ----
#pragma unroll
    for (int s = 0; s < NST - 1; s++) {
        const uint32_t st = sb + s * STAGE_BYTES;
        const __half* a = Ag + s * 64;
        const __half* b = Bg + s * 64;
#pragma unroll
        for (int i = 0; i < 4; i++)
            cpasync16(st + sAsw[i], a + (size_t)sArow[i] * DM + scol8);
#pragma unroll
        for (int i = 0; i < 8; i++)
            cpasync16(st + A_BYTES + sBsw[i], b + (size_t)sBrow[i] * DM + scol8);
        asm volatile("cp.async.commit_group;" ::: "memory");
    }

#pragma unroll 1
    for (int ks = 0; ks < 16; ks++) {
        asm volatile("cp.async.wait_group 1;" ::: "memory");
        __syncthreads();

        if (ks + NST - 1 < 16) {
            const int s = ks + NST - 1;
            const uint32_t st = sb + (s % NST) * STAGE_BYTES;
            const __half* a = Ag + s * 64;
            const __half* b = Bg + s * 64;
#pragma unroll
            for (int i = 0; i < 4; i++)
                cpasync16(st + sAsw[i], a + (size_t)sArow[i] * DM + scol8);
#pragma unroll
            for (int i = 0; i < 8; i++)
                cpasync16(st + A_BYTES + sBsw[i], b + (size_t)sBrow[i] * DM + scol8);
        }
        asm volatile("cp.async.commit_group;" ::: "memory");

        const uint32_t st = sb + (ks % NST) * STAGE_BYTES;
#pragma unroll
        for (int kk = 0; kk < 4; kk++) {
            uint32_t a[4][4], b[4][4];
#pragma unroll
            for (int mt = 0; mt < 4; mt++)
                ldsm4(a[mt], st + aOff[mt] + (((kk * 2 + aHi) ^ aSw[mt]) << 4));
#pragma unroll
            for (int np = 0; np < 4; np++)
                ldsm4(b[np], st + bOff[np] + (((kk * 2 + bHi) ^ bSw[np]) << 4));
#pragma unroll
            for (int mt = 0; mt < 4; mt++)
#pragma unroll
                for (int nt = 0; nt < 8; nt++)
                    mma_f16(acc[mt][nt], a[mt], &b[nt >> 1][(nt & 1) * 2]);
        }
    }

    // ---- epilogue ----
    if (MODE == 0) {
        __half* Cb = (n0 < 1024) ? g_Q : (n0 < 2048) ? g_K : g_V;
        const int col0 = (n0 & 1023) + wn * 64;
#pragma unroll
        for (int mt = 0; mt < 4; mt++) {
            const int r = m0 + wm * 64 + mt * 16 + (lane >> 2);
#pragma unroll
            for (int nt = 0; nt < 8; nt++) {
                const int c = col0 + nt * 8 + 2 * (lane & 3);
                *(__half2*)&Cb[(size_t)r * DM + c] =
                    __floats2half2_rn(acc[mt][nt][0], acc[mt][nt][1]);
                *(__half2*)&Cb[(size_t)(r + 8) * DM + c] =
                    __floats2half2_rn(acc[mt][nt][2], acc[mt][nt][3]);
            }
        }
    } else {
        const int col0 = n0 + wn * 64;
#pragma unroll
        for (int mt = 0; mt < 4; mt++) {
            const int r = m0 + wm * 64 + mt * 16 + (lane >> 2);
#pragma unroll
            for (int nt = 0; nt < 8; nt++) {
                const int c = col0 + nt * 8 + 2 * (lane & 3);
                const float b0 = bias[c], b1 = bias[c + 1];
                *(float2*)&Cout[(size_t)r * DM + c] =
                    make_float2(acc[mt][nt][0] + b0, acc[mt][nt][1] + b1);
                *(float2*)&Cout[(size_t)(r + 8) * DM + c] =
                    make_float2(acc[mt][nt][2] + b0, acc[mt][nt][3] + b1);
            }
        }
    }
}

// ---------------------------------------------------------------------------
// Attention-over-heads, fp16 in / fp16 out, fp32 math.
// One warp per token p. Scatter: MID[n, i*256 + (s>>4), (s&15)*64 + d]
// ---------------------------------------------------------------------------
__global__ void __launch_bounds__(64) attn_k() {
    __shared__ float sm[2][3536];
    const int lane = threadIdx.x & 31;
    const int w = threadIdx.x >> 5;
    const int p = blockIdx.x * 2 + w;

    const __half* q = g_Q + (size_t)p * DM;
    const __half* k = g_K + (size_t)p * DM;
    const __half* v = g_V + (size_t)p * DM;
    float* qs = sm[w];
    float* ks = qs + 1088;
    float* vs = ks + 1088;
    float* at = vs + 1088;

#pragma unroll
    for (int t = lane; t < 128; t += 32) {
        const int i = t >> 3;
        const int d = (t & 7) * 8;
        const int off = i * 68 + d;
        uint4 uq = *(const uint4*)(q + t * 8);
        uint4 uk = *(const uint4*)(k + t * 8);
        uint4 uv = *(const uint4*)(v + t * 8);
        const __half2* hq = (const __half2*)&uq;
        const __half2* hk = (const __half2*)&uk;
        const __half2* hv = (const __half2*)&uv;
        float2 f0, f1;
        f0 = __half22float2(hq[0]); f1 = __half22float2(hq[1]);
        *(float4*)&qs[off] = make_float4(f0.x, f0.y, f1.x, f1.y);
        f0 = __half22float2(hq[2]); f1 = __half22float2(hq[3]);
        *(float4*)&qs[off + 4] = make_float4(f0.x, f0.y, f1.x, f1.y);
        f0 = __half22float2(hk[0]); f1 = __half22float2(hk[1]);
        *(float4*)&ks[off] = make_float4(f0.x, f0.y, f1.x, f1.y);
        f0 = __half22float2(hk[2]); f1 = __half22float2(hk[3]);
        *(float4*)&ks[off + 4] = make_float4(f0.x, f0.y, f1.x, f1.y);
        f0 = __half22float2(hv[0]); f1 = __half22float2(hv[1]);
        *(float4*)&vs[off] = make_float4(f0.x, f0.y, f1.x, f1.y);
        f0 = __half22float2(hv[2]); f1 = __half22float2(hv[3]);
        *(float4*)&vs[off + 4] = make_float4(f0.x, f0.y, f1.x, f1.y);
    }
    __syncwarp();

    const int bi = lane >> 2;
    const int bj = lane & 3;
    float acc[2][4];
#pragma unroll
    for (int u = 0; u < 2; u++)
#pragma unroll
        for (int jv = 0; jv < 4; jv++) acc[u][jv] = 0.f;

#pragma unroll
    for (int d = 0; d < 64; d += 4) {
        float4 q0 = *(float4*)&qs[(2 * bi) * 68 + d];
        float4 q1 = *(float4*)&qs[(2 * bi + 1) * 68 + d];
#pragma unroll
        for (int jv = 0; jv < 4; jv++) {
            float4 kv = *(float4*)&ks[(4 * bj + jv) * 68 + d];
            acc[0][jv] += q0.x * kv.x + q0.y * kv.y + q0.z * kv.z + q0.w * kv.w;
            acc[1][jv] += q1.x * kv.x + q1.y * kv.y + q1.z * kv.z + q1.w * kv.w;
        }
    }
#pragma unroll
    for (int u = 0; u < 2; u++)
#pragma unroll
        for (int jv = 0; jv < 4; jv++)
            at[(2 * bi + u) * 17 + 4 * bj + jv] = acc[u][jv];
    __syncwarp();

    if (lane < 16) {
        float* row = &at[lane * 17];
        float m = row[0];
#pragma unroll
        for (int j = 1; j < 16; j++) m = fmaxf(m, row[j]);
        float ssum = 0.f;
#pragma unroll
        for (int j = 0; j < 16; j++) {
            float e = __expf((row[j] - m) * 0.125f);
            row[j] = e;
            ssum += e;
        }
        float inv = 1.f / ssum;
#pragma unroll
        for (int j = 0; j < 16; j++) row[j] *= inv;
    }
    __syncwarp();

    const int bd = lane & 3;
    float4 o[2][4];
#pragma unroll
    for (int u = 0; u < 2; u++)
#pragma unroll
        for (int v4 = 0; v4 < 4; v4++) o[u][v4] = make_float4(0.f, 0.f, 0.f, 0.f);

#pragma unroll
    for (int j = 0; j < 16; j++) {
        float a0 = at[(2 * bi) * 17 + j];
        float a1 = at[(2 * bi + 1) * 17 + j];
#pragma unroll
        for (int v4 = 0; v4 < 4; v4++) {
            float4 vv = *(float4*)&vs[j * 68 + (4 * bd + v4) * 4];
            o[0][v4].x += a0 * vv.x; o[0][v4].y += a0 * vv.y;
            o[0][v4].z += a0 * vv.z; o[0][v4].w += a0 * vv.w;
            o[1][v4].x += a1 * vv.x; o[1][v4].y += a1 * vv.y;
            o[1][v4].z += a1 * vv.z; o[1][v4].w += a1 * vv.w;
        }
    }

    const int n = p >> 12;
    const int s = p & 4095;
    const size_t base = (size_t)n * SEQ * DM + (size_t)(s >> 4) * DM + (size_t)(s & 15) * 64;
#pragma unroll
    for (int u = 0; u < 2; u++) {
        const int i = 2 * bi + u;
        const size_t rowoff = base + (size_t)i * 256 * DM;
#pragma unroll
        for (int v4 = 0; v4 < 4; v4++) {
            float4 ov = o[u][v4];
            uint2 wv;
            *(__half2*)&wv.x = __floats2half2_rn(ov.x, ov.y);
            *(__half2*)&wv.y = __floats2half2_rn(ov.z, ov.w);
            *(uint2*)&g_MID[rowoff + (4 * bd + v4) * 4] = wv;
        }
    }
}

extern "C" void kernel_launch(void* const* d_in, const int* in_sizes, int n_in,
                              void* d_out, int out_size) {
    (void)in_sizes; (void)n_in; (void)out_size;
    const float* x  = (const float*)d_in[0];
    const float* Wq = (const float*)d_in[1];
    const float* Wk = (const float*)d_in[2];
    const float* Wv = (const float*)d_in[3];
    const float* Wo = (const float*)d_in[4];
    const float* bo = (const float*)d_in[5];
    float* out = (float*)d_out;

    cudaFuncSetAttribute(gemm_h<0>, cudaFuncAttributeMaxDynamicSharedMemorySize, GSMEM);
    cudaFuncSetAttribute(gemm_h<1>, cudaFuncAttributeMaxDynamicSharedMemorySize, GSMEM);

    __half* gX; __half* gW; __half* gWo;
    cudaGetSymbolAddress((void**)&gX, g_X);
    cudaGetSymbolAddress((void**)&gW, g_W);
    cudaGetSymbolAddress((void**)&gWo, g_Wo);

    // fp32 -> fp16 converts
    cvt_h<<<MTOT * DM / 8 / 256, 256>>>((const float4*)x, (uint4*)gX, MTOT * DM / 8);
    cvt_h<<<512, 256>>>((const float4*)Wq, (uint4*)gW, DM * DM / 8);
    cvt_h<<<512, 256>>>((const float4*)Wk, (uint4*)(gW + (size_t)DM * DM), DM * DM / 8);
    cvt_h<<<512, 256>>>((const float4*)Wv, (uint4*)(gW + (size_t)2 * DM * DM), DM * DM / 8);
    cvt_h<<<512, 256>>>((const float4*)Wo, (uint4*)gWo, DM * DM / 8);

    // 1) fused QKV projection (N = 3072)
    gemm_h<0><<<dim3(12, 256), 256, GSMEM>>>(nullptr, nullptr);
    // 2) attention-over-heads + scrambled reshape (fp16 out)
    attn_k<<<MTOT / 2, 64>>>();
    // 3) output projection + bias (fp32 out)
    gemm_h<1><<<dim3(4, 256), 256, GSMEM>>>(bo, out);
}

// round 8
// speedup vs baseline: 1.1030x; 1.1030x over previous
#include <cuda_runtime.h>
#include <cuda_fp16.h>
#include <cstdint>

#define SEQ 4096
#define DM 1024
#define MTOT 32768

// ---- scratch (device globals: sanctioned no-alloc workaround) ----
__device__ __half g_Q[(size_t)MTOT * DM];
__device__ __half g_K[(size_t)MTOT * DM];
__device__ __half g_V[(size_t)MTOT * DM];
__device__ __half g_MID[(size_t)MTOT * DM];
__device__ __half g_X[(size_t)MTOT * DM];         // fp16 x
__device__ __half g_W[(size_t)3 * DM * DM];       // fp16 [Wq;Wk;Wv]
__device__ __half g_Wo[(size_t)DM * DM];          // fp16 Wo

// ---------------------------------------------------------------------------
// helpers
// ---------------------------------------------------------------------------
__device__ __forceinline__ uint32_t smem_u32(const void* p) {
    uint32_t a;
    asm("{ .reg .u64 t; cvta.to.shared.u64 t, %1; cvt.u32.u64 %0, t; }" : "=r"(a) : "l"(p));
    return a;
}
__device__ __forceinline__ void cpasync16(uint32_t dst, const void* src) {
    asm volatile("cp.async.cg.shared.global [%0], [%1], 16;" :: "r"(dst), "l"(src) : "memory");
}
__device__ __forceinline__ void ldsm4(uint32_t* r, uint32_t addr) {
    asm volatile("ldmatrix.sync.aligned.m8n8.x4.shared.b16 {%0,%1,%2,%3}, [%4];"
                 : "=r"(r[0]), "=r"(r[1]), "=r"(r[2]), "=r"(r[3]) : "r"(addr));
}
__device__ __forceinline__ void mma_f16(float* c, const uint32_t* a, const uint32_t* b) {
    asm volatile(
        "mma.sync.aligned.m16n8k16.row.col.f32.f16.f16.f32 "
        "{%0,%1,%2,%3}, {%4,%5,%6,%7}, {%8,%9}, {%0,%1,%2,%3};\n"
        : "+f"(c[0]), "+f"(c[1]), "+f"(c[2]), "+f"(c[3])
        : "r"(a[0]), "r"(a[1]), "r"(a[2]), "r"(a[3]), "r"(b[0]), "r"(b[1]));
}

// ---------------------------------------------------------------------------
// fp32 -> fp16 convert (8 elements / thread)
// ---------------------------------------------------------------------------
__global__ void __launch_bounds__(256) cvt_h(const float4* __restrict__ src,
                                             uint4* __restrict__ dst, int n8) {
    int i = blockIdx.x * 256 + threadIdx.x;
    if (i < n8) {
        float4 a = src[2 * i], b = src[2 * i + 1];
        uint4 o;
        *(__half2*)&o.x = __floats2half2_rn(a.x, a.y);
        *(__half2*)&o.y = __floats2half2_rn(a.z, a.w);
        *(__half2*)&o.z = __floats2half2_rn(b.x, b.y);
        *(__half2*)&o.w = __floats2half2_rn(b.z, b.w);
        dst[i] = o;
    }
}

// ---------------------------------------------------------------------------
// fp16 GEMM: C[m,n] = sum_k A[m,k]*B[n,k]. Tile 128x128, BK=64 halves (128B
// rows, XOR-16B swizzle -> conflict-free cp.async stores AND ldmatrix loads).
// 128 threads (4 warps), warp grid 2(m) x 2(n), warp tile 64x64 -> 128 B of
// smem fragment reads per MMA (75% of the 128B/cyc crossbar at full tensor
// rate, vs 100% for the 64x32 warp tile). 3-stage cp.async pipeline, 96KB
// smem -> 2 CTAs/SM for latency cover.
// MODE 0: A=g_X, B=g_W (3072 rows), C -> g_Q/g_K/g_V (half). grid (24, 256)
// MODE 1: A=g_MID, B=g_Wo, C = out fp32 + bias.              grid (8, 256)
// ---------------------------------------------------------------------------
#define AB_BYTES 16384                     // 128 rows * 128B
#define STAGE_BYTES (2 * AB_BYTES)         // 32768
#define NST 3
#define GSMEM (NST * STAGE_BYTES)          // 98304

template <int MODE>
__global__ void __launch_bounds__(128, 2) gemm_h(const float* __restrict__ bias,
                                                 float* __restrict__ Cout) {
    extern __shared__ uint8_t sm_raw[];
    const uint32_t sb = smem_u32(sm_raw);
    const int tid = threadIdx.x;
    const int lane = tid & 31;
    const int wid = tid >> 5;
    const int wm = wid >> 1;         // 0..1 (m, 64 rows)
    const int wn = wid & 1;          // 0..1 (n, 64 cols)

    const int m0 = blockIdx.y * 128;
    const int n0 = blockIdx.x * 128;
    const __half* A = (MODE == 0) ? g_X : g_MID;
    const __half* B = (MODE == 0) ? g_W : g_Wo;
    const __half* Ag = A + (size_t)m0 * DM;
    const __half* Bg = B + (size_t)n0 * DM;

    // cp.async: 1024 A-chunks + 1024 B-chunks of 16B per stage, 8+8 per thread
    // chunk id = tid + i*128 -> row = id>>3 (0..127), c = id&7; swizzle c^(r&7)
    int srow[8], ssw[8];
#pragma unroll
    for (int i = 0; i < 8; i++) {
        int id = tid + i * 128;
        int r = id >> 3, c = id & 7;
        srow[i] = r;
        ssw[i] = r * 128 + ((c ^ (r & 7)) << 4);
    }
    const int scol8 = (tid & 7) * 8;   // gmem half-offset of this thread's chunk

    // ldmatrix bases: A frag mt rows wm*64+mt*16+(lane&15); hi chunk = lane>>4
    uint32_t aOff[4]; int aSw[4];
    const int aHi = lane >> 4;
#pragma unroll
    for (int mt = 0; mt < 4; mt++) {
        int r = wm * 64 + mt * 16 + (lane & 15);
        aOff[mt] = r * 128;
        aSw[mt] = r & 7;
    }
    // B frag np rows wn*64+np*16+((lane>>4)<<3)+(lane&7); hi = (lane>>3)&1
    uint32_t bOff[4]; int bSw[4];
    const int bHi = (lane >> 3) & 1;
#pragma unroll
    for (int np = 0; np < 4; np++) {
        int r = wn * 64 + np * 16 + ((lane >> 4) << 3) + (lane & 7);
        bOff[np] = AB_BYTES + r * 128;
        bSw[np] = r & 7;
    }

    float acc[4][8][4];
#pragma unroll
    for (int mt = 0; mt < 4; mt++)
#pragma unroll
        for (int nt = 0; nt < 8; nt++)
#pragma unroll
            for (int i = 0; i < 4; i++) acc[mt][nt][i] = 0.f;

    // ---- prologue: stages 0,1 ----
#pragma unroll
    for (int s = 0; s < NST - 1; s++) {
        const uint32_t st = sb + s * STAGE_BYTES;
        const __half* a = Ag + s * 64;
        const __half* b = Bg + s * 64;
#pragma unroll
        for (int i = 0; i < 8; i++) {
            cpasync16(st + ssw[i], a + (size_t)srow[i] * DM + scol8);
            cpasync16(st + AB_BYTES + ssw[i], b + (size_t)srow[i] * DM + scol8);
        }
        asm volatile("cp.async.commit_group;" ::: "memory");
    }

#pragma unroll 1
    for (int ks = 0; ks < 16; ks++) {
        asm volatile("cp.async.wait_group 1;" ::: "memory");
        __syncthreads();

        if (ks + NST - 1 < 16) {
            const int s = ks + NST - 1;
            const uint32_t st = sb + (s % NST) * STAGE_BYTES;
            const __half* a = Ag + s * 64;
            const __half* b = Bg + s * 64;
#pragma unroll
            for (int i = 0; i < 8; i++) {
                cpasync16(st + ssw[i], a + (size_t)srow[i] * DM + scol8);
                cpasync16(st + AB_BYTES + ssw[i], b + (size_t)srow[i] * DM + scol8);
            }
        }
        asm volatile("cp.async.commit_group;" ::: "memory");

        const uint32_t st = sb + (ks % NST) * STAGE_BYTES;
#pragma unroll
        for (int kk = 0; kk < 4; kk++) {
            uint32_t a[4][4], b[4][4];
#pragma unroll
            for (int mt = 0; mt < 4; mt++)
                ldsm4(a[mt], st + aOff[mt] + (((kk * 2 + aHi) ^ aSw[mt]) << 4));
#pragma unroll
            for (int np = 0; np < 4; np++)
                ldsm4(b[np], st + bOff[np] + (((kk * 2 + bHi) ^ bSw[np]) << 4));
#pragma unroll
            for (int mt = 0; mt < 4; mt++)
#pragma unroll
                for (int nt = 0; nt < 8; nt++)
                    mma_f16(acc[mt][nt], a[mt], &b[nt >> 1][(nt & 1) * 2]);
        }
    }

    // ---- epilogue ----
    if (MODE == 0) {
        __half* Cb = (n0 < 1024) ? g_Q : (n0 < 2048) ? g_K : g_V;
        const int col0 = (n0 & 1023) + wn * 64;
#pragma unroll
        for (int mt = 0; mt < 4; mt++) {
            const int r = m0 + wm * 64 + mt * 16 + (lane >> 2);
#pragma unroll
            for (int nt = 0; nt < 8; nt++) {
                const int c = col0 + nt * 8 + 2 * (lane & 3);
                *(__half2*)&Cb[(size_t)r * DM + c] =
                    __floats2half2_rn(acc[mt][nt][0], acc[mt][nt][1]);
                *(__half2*)&Cb[(size_t)(r + 8) * DM + c] =
                    __floats2half2_rn(acc[mt][nt][2], acc[mt][nt][3]);
            }
        }
    } else {
        const int col0 = n0 + wn * 64;
#pragma unroll
        for (int mt = 0; mt < 4; mt++) {
            const int r = m0 + wm * 64 + mt * 16 + (lane >> 2);
#pragma unroll
            for (int nt = 0; nt < 8; nt++) {
                const int c = col0 + nt * 8 + 2 * (lane & 3);
                const float b0 = bias[c], b1 = bias[c + 1];
                *(float2*)&Cout[(size_t)r * DM + c] =
                    make_float2(acc[mt][nt][0] + b0, acc[mt][nt][1] + b1);
                *(float2*)&Cout[(size_t)(r + 8) * DM + c] =
                    make_float2(acc[mt][nt][2] + b0, acc[mt][nt][3] + b1);
            }
        }
    }
}

// ---------------------------------------------------------------------------
// Attention-over-heads, fp16 in / fp16 out, fp32 math.
// One warp per token p. Scatter: MID[n, i*256 + (s>>4), (s&15)*64 + d]
// ---------------------------------------------------------------------------
__global__ void __launch_bounds__(64) attn_k() {
    __shared__ float sm[2][3536];
    const int lane = threadIdx.x & 31;
    const int w = threadIdx.x >> 5;
    const int p = blockIdx.x * 2 + w;

    const __half* q = g_Q + (size_t)p * DM;
    const __half* k = g_K + (size_t)p * DM;
    const __half* v = g_V + (size_t)p * DM;
    float* qs = sm[w];
    float* ks = qs + 1088;
    float* vs = ks + 1088;
    float* at = vs + 1088;

#pragma unroll
    for (int t = lane; t < 128; t += 32) {
        const int i = t >> 3;
        const int d = (t & 7) * 8;
        const int off = i * 68 + d;
        uint4 uq = *(const uint4*)(q + t * 8);
        uint4 uk = *(const uint4*)(k + t * 8);
        uint4 uv = *(const uint4*)(v + t * 8);
        const __half2* hq = (const __half2*)&uq;
        const __half2* hk = (const __half2*)&uk;
        const __half2* hv = (const __half2*)&uv;
        float2 f0, f1;
        f0 = __half22float2(hq[0]); f1 = __half22float2(hq[1]);
        *(float4*)&qs[off] = make_float4(f0.x, f0.y, f1.x, f1.y);
        f0 = __half22float2(hq[2]); f1 = __half22float2(hq[3]);
        *(float4*)&qs[off + 4] = make_float4(f0.x, f0.y, f1.x, f1.y);
        f0 = __half22float2(hk[0]); f1 = __half22float2(hk[1]);
        *(float4*)&ks[off] = make_float4(f0.x, f0.y, f1.x, f1.y);
        f0 = __half22float2(hk[2]); f1 = __half22float2(hk[3]);
        *(float4*)&ks[off + 4] = make_float4(f0.x, f0.y, f1.x, f1.y);
        f0 = __half22float2(hv[0]); f1 = __half22float2(hv[1]);
        *(float4*)&vs[off] = make_float4(f0.x, f0.y, f1.x, f1.y);
        f0 = __half22float2(hv[2]); f1 = __half22float2(hv[3]);
        *(float4*)&vs[off + 4] = make_float4(f0.x, f0.y, f1.x, f1.y);
    }
    __syncwarp();

    const int bi = lane >> 2;
    const int bj = lane & 3;
    float acc[2][4];
#pragma unroll
    for (int u = 0; u < 2; u++)
#pragma unroll
        for (int jv = 0; jv < 4; jv++) acc[u][jv] = 0.f;

#pragma unroll
    for (int d = 0; d < 64; d += 4) {
        float4 q0 = *(float4*)&qs[(2 * bi) * 68 + d];
        float4 q1 = *(float4*)&qs[(2 * bi + 1) * 68 + d];
#pragma unroll
        for (int jv = 0; jv < 4; jv++) {
            float4 kv = *(float4*)&ks[(4 * bj + jv) * 68 + d];
            acc[0][jv] += q0.x * kv.x + q0.y * kv.y + q0.z * kv.z + q0.w * kv.w;
            acc[1][jv] += q1.x * kv.x + q1.y * kv.y + q1.z * kv.z + q1.w * kv.w;
        }
    }
#pragma unroll
    for (int u = 0; u < 2; u++)
#pragma unroll
        for (int jv = 0; jv < 4; jv++)
            at[(2 * bi + u) * 17 + 4 * bj + jv] = acc[u][jv];
    __syncwarp();

    if (lane < 16) {
        float* row = &at[lane * 17];
        float m = row[0];
#pragma unroll
        for (int j = 1; j < 16; j++) m = fmaxf(m, row[j]);
        float ssum = 0.f;
#pragma unroll
        for (int j = 0; j < 16; j++) {
            float e = __expf((row[j] - m) * 0.125f);
            row[j] = e;
            ssum += e;
        }
        float inv = 1.f / ssum;
#pragma unroll
        for (int j = 0; j < 16; j++) row[j] *= inv;
    }
    __syncwarp();

    const int bd = lane & 3;
    float4 o[2][4];
#pragma unroll
    for (int u = 0; u < 2; u++)
#pragma unroll
        for (int v4 = 0; v4 < 4; v4++) o[u][v4] = make_float4(0.f, 0.f, 0.f, 0.f);

#pragma unroll
    for (int j = 0; j < 16; j++) {
        float a0 = at[(2 * bi) * 17 + j];
        float a1 = at[(2 * bi + 1) * 17 + j];
#pragma unroll
        for (int v4 = 0; v4 < 4; v4++) {
            float4 vv = *(float4*)&vs[j * 68 + (4 * bd + v4) * 4];
            o[0][v4].x += a0 * vv.x; o[0][v4].y += a0 * vv.y;
            o[0][v4].z += a0 * vv.z; o[0][v4].w += a0 * vv.w;
            o[1][v4].x += a1 * vv.x; o[1][v4].y += a1 * vv.y;
            o[1][v4].z += a1 * vv.z; o[1][v4].w += a1 * vv.w;
        }
    }

    const int n = p >> 12;
    const int s = p & 4095;
    const size_t base = (size_t)n * SEQ * DM + (size_t)(s >> 4) * DM + (size_t)(s & 15) * 64;
#pragma unroll
    for (int u = 0; u < 2; u++) {
        const int i = 2 * bi + u;
        const size_t rowoff = base + (size_t)i * 256 * DM;
#pragma unroll
        for (int v4 = 0; v4 < 4; v4++) {
            float4 ov = o[u][v4];
            uint2 wv;
            *(__half2*)&wv.x = __floats2half2_rn(ov.x, ov.y);
            *(__half2*)&wv.y = __floats2half2_rn(ov.z, ov.w);
            *(uint2*)&g_MID[rowoff + (4 * bd + v4) * 4] = wv;
        }
    }
}

extern "C" void kernel_launch(void* const* d_in, const int* in_sizes, int n_in,
                              void* d_out, int out_size) {
    (void)in_sizes; (void)n_in; (void)out_size;
    const float* x  = (const float*)d_in[0];
    const float* Wq = (const float*)d_in[1];
    const float* Wk = (const float*)d_in[2];
    const float* Wv = (const float*)d_in[3];
    const float* Wo = (const float*)d_in[4];
    const float* bo = (const float*)d_in[5];
    float* out = (float*)d_out;

    cudaFuncSetAttribute(gemm_h<0>, cudaFuncAttributeMaxDynamicSharedMemorySize, GSMEM);
    cudaFuncSetAttribute(gemm_h<1>, cudaFuncAttributeMaxDynamicSharedMemorySize, GSMEM);

    __half* gX; __half* gW; __half* gWo;
    cudaGetSymbolAddress((void**)&gX, g_X);
    cudaGetSymbolAddress((void**)&gW, g_W);
    cudaGetSymbolAddress((void**)&gWo, g_Wo);

    // fp32 -> fp16 converts
    cvt_h<<<MTOT * DM / 8 / 256, 256>>>((const float4*)x, (uint4*)gX, MTOT * DM / 8);
    cvt_h<<<512, 256>>>((const float4*)Wq, (uint4*)gW, DM * DM / 8);
    cvt_h<<<512, 256>>>((const float4*)Wk, (uint4*)(gW + (size_t)DM * DM), DM * DM / 8);
    cvt_h<<<512, 256>>>((const float4*)Wv, (uint4*)(gW + (size_t)2 * DM * DM), DM * DM / 8);
    cvt_h<<<512, 256>>>((const float4*)Wo, (uint4*)gWo, DM * DM / 8);

    // 1) fused QKV projection (N = 3072)
    gemm_h<0><<<dim3(24, 256), 128, GSMEM>>>(nullptr, nullptr);
    // 2) attention-over-heads + scrambled reshape (fp16 out)
    attn_k<<<MTOT / 2, 64>>>();
    // 3) output projection + bias (fp32 out)
    gemm_h<1><<<dim3(8, 256), 128, GSMEM>>>(bo, out);
}

// round 9
// speedup vs baseline: 1.1654x; 1.0565x over previous
#include <cuda_runtime.h>
#include <cuda_fp16.h>
#include <cstdint>

#define SEQ 4096
#define DM 1024
#define MTOT 32768

// ---- scratch (device globals: sanctioned no-alloc workaround) ----
__device__ __half g_Q[(size_t)MTOT * DM];
__device__ __half g_K[(size_t)MTOT * DM];
__device__ __half g_V[(size_t)MTOT * DM];
__device__ __half g_MID[(size_t)MTOT * DM];
__device__ __half g_X[(size_t)MTOT * DM];         // fp16 x
__device__ __half g_W[(size_t)3 * DM * DM];       // fp16 [Wq;Wk;Wv]
__device__ __half g_Wo[(size_t)DM * DM];          // fp16 Wo

// ---------------------------------------------------------------------------
// helpers
// ---------------------------------------------------------------------------
__device__ __forceinline__ uint32_t smem_u32(const void* p) {
    uint32_t a;
    asm("{ .reg .u64 t; cvta.to.shared.u64 t, %1; cvt.u32.u64 %0, t; }" : "=r"(a) : "l"(p));
    return a;
}
__device__ __forceinline__ void cpasync16(uint32_t dst, const void* src) {
    asm volatile("cp.async.cg.shared.global [%0], [%1], 16;" :: "r"(dst), "l"(src) : "memory");
}
__device__ __forceinline__ void ldsm4(uint32_t* r, uint32_t addr) {
    asm volatile("ldmatrix.sync.aligned.m8n8.x4.shared.b16 {%0,%1,%2,%3}, [%4];"
                 : "=r"(r[0]), "=r"(r[1]), "=r"(r[2]), "=r"(r[3]) : "r"(addr));
}
__device__ __forceinline__ void mma_f16(float* c, const uint32_t* a, const uint32_t* b) {
    asm volatile(
        "mma.sync.aligned.m16n8k16.row.col.f32.f16.f16.f32 "
        "{%0,%1,%2,%3}, {%4,%5,%6,%7}, {%8,%9}, {%0,%1,%2,%3};\n"
        : "+f"(c[0]), "+f"(c[1]), "+f"(c[2]), "+f"(c[3])
        : "r"(a[0]), "r"(a[1]), "r"(a[2]), "r"(a[3]), "r"(b[0]), "r"(b[1]));
}

// ---------------------------------------------------------------------------
// fp32 -> fp16 convert (8 elements / thread)
// ---------------------------------------------------------------------------
__global__ void __launch_bounds__(256) cvt_h(const float4* __restrict__ src,
                                             uint4* __restrict__ dst, int n8) {
    int i = blockIdx.x * 256 + threadIdx.x;
    if (i < n8) {
        float4 a = src[2 * i], b = src[2 * i + 1];
        uint4 o;
        *(__half2*)&o.x = __floats2half2_rn(a.x, a.y);
        *(__half2*)&o.y = __floats2half2_rn(a.z, a.w);
        *(__half2*)&o.z = __floats2half2_rn(b.x, b.y);
        *(__half2*)&o.w = __floats2half2_rn(b.z, b.w);
        dst[i] = o;
    }
}

// ---------------------------------------------------------------------------
// fp16 GEMM: C[m,n] = sum_k A[m,k]*B[n,k]. Tile 128x128, BK=64 halves (128B
// rows, XOR-16B swizzle -> conflict-free cp.async stores AND ldmatrix loads).
// 128 threads (4 warps), warp grid 2x2, warp tile 64x64. 3-stage cp.async
// pipeline, 96KB smem -> 2 CTAs/SM. Inner loop: register double-buffered
// ldmatrix fragments (load kk+1 under kk's MMA stream); first fragment burst
// issued BEFORE the cp.async stores so tensor work starts immediately after
// the barrier.
// MODE 0: A=g_X, B=g_W (3072 rows), C -> g_Q/g_K/g_V (half). grid (24, 256)
// MODE 1: A=g_MID, B=g_Wo, C = out fp32 + bias.              grid (8, 256)
// ---------------------------------------------------------------------------
#define AB_BYTES 16384                     // 128 rows * 128B
#define STAGE_BYTES (2 * AB_BYTES)         // 32768
#define NST 3
#define GSMEM (NST * STAGE_BYTES)          // 98304

template <int MODE>
__global__ void __launch_bounds__(128, 2) gemm_h(const float* __restrict__ bias,
                                                 float* __restrict__ Cout) {
    extern __shared__ uint8_t sm_raw[];
    const uint32_t sb = smem_u32(sm_raw);
    const int tid = threadIdx.x;
    const int lane = tid & 31;
    const int wid = tid >> 5;
    const int wm = wid >> 1;         // 0..1 (m, 64 rows)
    const int wn = wid & 1;          // 0..1 (n, 64 cols)

    const int m0 = blockIdx.y * 128;
    const int n0 = blockIdx.x * 128;
    const __half* A = (MODE == 0) ? g_X : g_MID;
    const __half* B = (MODE == 0) ? g_W : g_Wo;
    const __half* Ag = A + (size_t)m0 * DM;
    const __half* Bg = B + (size_t)n0 * DM;

    // cp.async: 1024 A-chunks + 1024 B-chunks of 16B per stage, 8+8 per thread
    int srow[8], ssw[8];
#pragma unroll
    for (int i = 0; i < 8; i++) {
        int id = tid + i * 128;
        int r = id >> 3, c = id & 7;
        srow[i] = r;
        ssw[i] = r * 128 + ((c ^ (r & 7)) << 4);
    }
    const int scol8 = (tid & 7) * 8;

    // ldmatrix bases
    uint32_t aOff[4]; int aSw[4];
    const int aHi = lane >> 4;
#pragma unroll
    for (int mt = 0; mt < 4; mt++) {
        int r = wm * 64 + mt * 16 + (lane & 15);
        aOff[mt] = r * 128;
        aSw[mt] = r & 7;
    }
    uint32_t bOff[4]; int bSw[4];
    const int bHi = (lane >> 3) & 1;
#pragma unroll
    for (int np = 0; np < 4; np++) {
        int r = wn * 64 + np * 16 + ((lane >> 4) << 3) + (lane & 7);
        bOff[np] = AB_BYTES + r * 128;
        bSw[np] = r & 7;
    }

    float acc[4][8][4];
#pragma unroll
    for (int mt = 0; mt < 4; mt++)
#pragma unroll
        for (int nt = 0; nt < 8; nt++)
#pragma unroll
            for (int i = 0; i < 4; i++) acc[mt][nt][i] = 0.f;

    // ---- prologue: stages 0,1 ----
#pragma unroll
    for (int s = 0; s < NST - 1; s++) {
        const uint32_t st = sb + s * STAGE_BYTES;
        const __half* a = Ag + s * 64;
        const __half* b = Bg + s * 64;
#pragma unroll
        for (int i = 0; i < 8; i++) {
            cpasync16(st + ssw[i], a + (size_t)srow[i] * DM + scol8);
            cpasync16(st + AB_BYTES + ssw[i], b + (size_t)srow[i] * DM + scol8);
        }
        asm volatile("cp.async.commit_group;" ::: "memory");
    }

    uint32_t af[2][4][4], bf[2][4][4];   // double-buffered fragments

#pragma unroll 1
    for (int ks = 0; ks < 16; ks++) {
        asm volatile("cp.async.wait_group 1;" ::: "memory");
        __syncthreads();

        const uint32_t st = sb + (ks % NST) * STAGE_BYTES;

        // fragments for kk=0 FIRST (tensor work starts immediately)
#pragma unroll
        for (int mt = 0; mt < 4; mt++)
            ldsm4(af[0][mt], st + aOff[mt] + ((aHi ^ aSw[mt]) << 4));
#pragma unroll
        for (int np = 0; np < 4; np++)
            ldsm4(bf[0][np], st + bOff[np] + ((bHi ^ bSw[np]) << 4));

        // then stream the next stage's cp.async under the MMA shadow
        if (ks + NST - 1 < 16) {
            const int s = ks + NST - 1;
            const uint32_t stw = sb + (s % NST) * STAGE_BYTES;
            const __half* a = Ag + s * 64;
            const __half* b = Bg + s * 64;
#pragma unroll
            for (int i = 0; i < 8; i++) {
                cpasync16(stw + ssw[i], a + (size_t)srow[i] * DM + scol8);
                cpasync16(stw + AB_BYTES + ssw[i], b + (size_t)srow[i] * DM + scol8);
            }
        }
        asm volatile("cp.async.commit_group;" ::: "memory");

#pragma unroll
        for (int kk = 0; kk < 4; kk++) {
            const int cur = kk & 1, nxt = cur ^ 1;
            if (kk < 3) {   // prefetch kk+1 fragments under this burst's MMAs
#pragma unroll
                for (int mt = 0; mt < 4; mt++)
                    ldsm4(af[nxt][mt],
                          st + aOff[mt] + ((((kk + 1) * 2 + aHi) ^ aSw[mt]) << 4));
#pragma unroll
                for (int np = 0; np < 4; np++)
                    ldsm4(bf[nxt][np],
                          st + bOff[np] + ((((kk + 1) * 2 + bHi) ^ bSw[np]) << 4));
            }
#pragma unroll
            for (int mt = 0; mt < 4; mt++)
#pragma unroll
                for (int nt = 0; nt < 8; nt++)
                    mma_f16(acc[mt][nt], af[cur][mt], &bf[cur][nt >> 1][(nt & 1) * 2]);
        }
    }

    // ---- epilogue ----
    if (MODE == 0) {
        __half* Cb = (n0 < 1024) ? g_Q : (n0 < 2048) ? g_K : g_V;
        const int col0 = (n0 & 1023) + wn * 64;
#pragma unroll
        for (int mt = 0; mt < 4; mt++) {
            const int r = m0 + wm * 64 + mt * 16 + (lane >> 2);
#pragma unroll
            for (int nt = 0; nt < 8; nt++) {
                const int c = col0 + nt * 8 + 2 * (lane & 3);
                *(__half2*)&Cb[(size_t)r * DM + c] =
                    __floats2half2_rn(acc[mt][nt][0], acc[mt][nt][1]);
                *(__half2*)&Cb[(size_t)(r + 8) * DM + c] =
                    __floats2half2_rn(acc[mt][nt][2], acc[mt][nt][3]);
            }
        }
    } else {
        const int col0 = n0 + wn * 64;
#pragma unroll
        for (int mt = 0; mt < 4; mt++) {
            const int r = m0 + wm * 64 + mt * 16 + (lane >> 2);
#pragma unroll
            for (int nt = 0; nt < 8; nt++) {
                const int c = col0 + nt * 8 + 2 * (lane & 3);
                const float b0 = bias[c], b1 = bias[c + 1];
                *(float2*)&Cout[(size_t)r * DM + c] =
                    make_float2(acc[mt][nt][0] + b0, acc[mt][nt][1] + b1);
                *(float2*)&Cout[(size_t)(r + 8) * DM + c] =
                    make_float2(acc[mt][nt][2] + b0, acc[mt][nt][3] + b1);
            }
        }
    }
}

// ---------------------------------------------------------------------------
// Attention-over-heads, fp16 in / fp16 out, fp32 math.
// One warp per token p. Scatter: MID[n, i*256 + (s>>4), (s&15)*64 + d]
// ---------------------------------------------------------------------------
__global__ void __launch_bounds__(64) attn_k() {
    __shared__ float sm[2][3536];
    const int lane = threadIdx.x & 31;
    const int w = threadIdx.x >> 5;
    const int p = blockIdx.x * 2 + w;

    const __half* q = g_Q + (size_t)p * DM;
    const __half* k = g_K + (size_t)p * DM;
    const __half* v = g_V + (size_t)p * DM;
    float* qs = sm[w];
    float* ks = qs + 1088;
    float* vs = ks + 1088;
    float* at = vs + 1088;

#pragma unroll
    for (int t = lane; t < 128; t += 32) {
        const int i = t >> 3;
        const int d = (t & 7) * 8;
        const int off = i * 68 + d;
        uint4 uq = *(const uint4*)(q + t * 8);
        uint4 uk = *(const uint4*)(k + t * 8);
        uint4 uv = *(const uint4*)(v + t * 8);
        const __half2* hq = (const __half2*)&uq;
        const __half2* hk = (const __half2*)&uk;
        const __half2* hv = (const __half2*)&uv;
        float2 f0, f1;
        f0 = __half22float2(hq[0]); f1 = __half22float2(hq[1]);
        *(float4*)&qs[off] = make_float4(f0.x, f0.y, f1.x, f1.y);
        f0 = __half22float2(hq[2]); f1 = __half22float2(hq[3]);
        *(float4*)&qs[off + 4] = make_float4(f0.x, f0.y, f1.x, f1.y);
        f0 = __half22float2(hk[0]); f1 = __half22float2(hk[1]);
        *(float4*)&ks[off] = make_float4(f0.x, f0.y, f1.x, f1.y);
        f0 = __half22float2(hk[2]); f1 = __half22float2(hk[3]);
        *(float4*)&ks[off + 4] = make_float4(f0.x, f0.y, f1.x, f1.y);
        f0 = __half22float2(hv[0]); f1 = __half22float2(hv[1]);
        *(float4*)&vs[off] = make_float4(f0.x, f0.y, f1.x, f1.y);
        f0 = __half22float2(hv[2]); f1 = __half22float2(hv[3]);
        *(float4*)&vs[off + 4] = make_float4(f0.x, f0.y, f1.x, f1.y);
    }
    __syncwarp();

    const int bi = lane >> 2;
    const int bj = lane & 3;
    float acc[2][4];
#pragma unroll
    for (int u = 0; u < 2; u++)
#pragma unroll
        for (int jv = 0; jv < 4; jv++) acc[u][jv] = 0.f;

#pragma unroll
    for (int d = 0; d < 64; d += 4) {
        float4 q0 = *(float4*)&qs[(2 * bi) * 68 + d];
        float4 q1 = *(float4*)&qs[(2 * bi + 1) * 68 + d];
#pragma unroll
        for (int jv = 0; jv < 4; jv++) {
            float4 kv = *(float4*)&ks[(4 * bj + jv) * 68 + d];
            acc[0][jv] += q0.x * kv.x + q0.y * kv.y + q0.z * kv.z + q0.w * kv.w;
            acc[1][jv] += q1.x * kv.x + q1.y * kv.y + q1.z * kv.z + q1.w * kv.w;
        }
    }
#pragma unroll
    for (int u = 0; u < 2; u++)
#pragma unroll
        for (int jv = 0; jv < 4; jv++)
            at[(2 * bi + u) * 17 + 4 * bj + jv] = acc[u][jv];
    __syncwarp();

    if (lane < 16) {
        float* row = &at[lane * 17];
        float m = row[0];
#pragma unroll
        for (int j = 1; j < 16; j++) m = fmaxf(m, row[j]);
        float ssum = 0.f;
#pragma unroll
        for (int j = 0; j < 16; j++) {
            float e = __expf((row[j] - m) * 0.125f);
            row[j] = e;
            ssum += e;
        }
        float inv = 1.f / ssum;
#pragma unroll
        for (int j = 0; j < 16; j++) row[j] *= inv;
    }
    __syncwarp();

    const int bd = lane & 3;
    float4 o[2][4];
#pragma unroll
    for (int u = 0; u < 2; u++)
#pragma unroll
        for (int v4 = 0; v4 < 4; v4++) o[u][v4] = make_float4(0.f, 0.f, 0.f, 0.f);

#pragma unroll
    for (int j = 0; j < 16; j++) {
        float a0 = at[(2 * bi) * 17 + j];
        float a1 = at[(2 * bi + 1) * 17 + j];
#pragma unroll
        for (int v4 = 0; v4 < 4; v4++) {
            float4 vv = *(float4*)&vs[j * 68 + (4 * bd + v4) * 4];
            o[0][v4].x += a0 * vv.x; o[0][v4].y += a0 * vv.y;
            o[0][v4].z += a0 * vv.z; o[0][v4].w += a0 * vv.w;
            o[1][v4].x += a1 * vv.x; o[1][v4].y += a1 * vv.y;
            o[1][v4].z += a1 * vv.z; o[1][v4].w += a1 * vv.w;
        }
    }

    const int n = p >> 12;
    const int s = p & 4095;
    const size_t base = (size_t)n * SEQ * DM + (size_t)(s >> 4) * DM + (size_t)(s & 15) * 64;
#pragma unroll
    for (int u = 0; u < 2; u++) {
        const int i = 2 * bi + u;
        const size_t rowoff = base + (size_t)i * 256 * DM;
#pragma unroll
        for (int v4 = 0; v4 < 4; v4++) {
            float4 ov = o[u][v4];
            uint2 wv;
            *(__half2*)&wv.x = __floats2half2_rn(ov.x, ov.y);
            *(__half2*)&wv.y = __floats2half2_rn(ov.z, ov.w);
            *(uint2*)&g_MID[rowoff + (4 * bd + v4) * 4] = wv;
        }
    }
}

extern "C" void kernel_launch(void* const* d_in, const int* in_sizes, int n_in,
                              void* d_out, int out_size) {
    (void)in_sizes; (void)n_in; (void)out_size;
    const float* x  = (const float*)d_in[0];
    const float* Wq = (const float*)d_in[1];
    const float* Wk = (const float*)d_in[2];
    const float* Wv = (const float*)d_in[3];
    const float* Wo = (const float*)d_in[4];
    const float* bo = (const float*)d_in[5];
    float* out = (float*)d_out;

    cudaFuncSetAttribute(gemm_h<0>, cudaFuncAttributeMaxDynamicSharedMemorySize, GSMEM);
    cudaFuncSetAttribute(gemm_h<1>, cudaFuncAttributeMaxDynamicSharedMemorySize, GSMEM);

    __half* gX; __half* gW; __half* gWo;
    cudaGetSymbolAddress((void**)&gX, g_X);
    cudaGetSymbolAddress((void**)&gW, g_W);
    cudaGetSymbolAddress((void**)&gWo, g_Wo);

    // fp32 -> fp16 converts
    cvt_h<<<MTOT * DM / 8 / 256, 256>>>((const float4*)x, (uint4*)gX, MTOT * DM / 8);
    cvt_h<<<512, 256>>>((const float4*)Wq, (uint4*)gW, DM * DM / 8);
    cvt_h<<<512, 256>>>((const float4*)Wk, (uint4*)(gW + (size_t)DM * DM), DM * DM / 8);
    cvt_h<<<512, 256>>>((const float4*)Wv, (uint4*)(gW + (size_t)2 * DM * DM), DM * DM / 8);
    cvt_h<<<512, 256>>>((const float4*)Wo, (uint4*)gWo, DM * DM / 8);

    // 1) fused QKV projection (N = 3072)
    gemm_h<0><<<dim3(24, 256), 128, GSMEM>>>(nullptr, nullptr);
    // 2) attention-over-heads + scrambled reshape (fp16 out)
    attn_k<<<MTOT / 2, 64>>>();
    // 3) output projection + bias (fp32 out)
    gemm_h<1><<<dim3(8, 256), 128, GSMEM>>>(bo, out);
}

// round 10
// speedup vs baseline: 1.3461x; 1.1550x over previous
#include <cuda_runtime.h>
#include <cuda_fp16.h>
#include <cstdint>

#define SEQ 4096
#define DM 1024
#define MTOT 32768

// ---- scratch (device globals: sanctioned no-alloc workaround) ----
__device__ __half g_Q[(size_t)MTOT * DM];
__device__ __half g_K[(size_t)MTOT * DM];
__device__ __half g_V[(size_t)MTOT * DM];
__device__ __half g_MID[(size_t)MTOT * DM];
__device__ __half g_X[(size_t)MTOT * DM];         // fp16 x
__device__ __half g_W[(size_t)3 * DM * DM];       // fp16 [Wq;Wk;Wv]
__device__ __half g_Wo[(size_t)DM * DM];          // fp16 Wo

// ---------------------------------------------------------------------------
// helpers
// ---------------------------------------------------------------------------
__device__ __forceinline__ uint32_t smem_u32(const void* p) {
    uint32_t a;
    asm("{ .reg .u64 t; cvta.to.shared.u64 t, %1; cvt.u32.u64 %0, t; }" : "=r"(a) : "l"(p));
    return a;
}
__device__ __forceinline__ void cpasync16(uint32_t dst, const void* src) {
    asm volatile("cp.async.cg.shared.global [%0], [%1], 16;" :: "r"(dst), "l"(src) : "memory");
}
__device__ __forceinline__ void ldsm4(uint32_t* r, uint32_t addr) {
    asm volatile("ldmatrix.sync.aligned.m8n8.x4.shared.b16 {%0,%1,%2,%3}, [%4];"
                 : "=r"(r[0]), "=r"(r[1]), "=r"(r[2]), "=r"(r[3]) : "r"(addr));
}
__device__ __forceinline__ void ldsm4t(uint32_t* r, uint32_t addr) {
    asm volatile("ldmatrix.sync.aligned.m8n8.x4.trans.shared.b16 {%0,%1,%2,%3}, [%4];"
                 : "=r"(r[0]), "=r"(r[1]), "=r"(r[2]), "=r"(r[3]) : "r"(addr));
}
__device__ __forceinline__ void mma_f16(float* c, const uint32_t* a, const uint32_t* b) {
    asm volatile(
        "mma.sync.aligned.m16n8k16.row.col.f32.f16.f16.f32 "
        "{%0,%1,%2,%3}, {%4,%5,%6,%7}, {%8,%9}, {%0,%1,%2,%3};\n"
        : "+f"(c[0]), "+f"(c[1]), "+f"(c[2]), "+f"(c[3])
        : "r"(a[0]), "r"(a[1]), "r"(a[2]), "r"(a[3]), "r"(b[0]), "r"(b[1]));
}

// ---------------------------------------------------------------------------
// fp32 -> fp16 converts
// ---------------------------------------------------------------------------
__global__ void __launch_bounds__(256) cvt_h(const float4* __restrict__ src,
                                             uint4* __restrict__ dst, int n8) {
    int i = blockIdx.x * 256 + threadIdx.x;
    if (i < n8) {
        float4 a = src[2 * i], b = src[2 * i + 1];
        uint4 o;
        *(__half2*)&o.x = __floats2half2_rn(a.x, a.y);
        *(__half2*)&o.y = __floats2half2_rn(a.z, a.w);
        *(__half2*)&o.z = __floats2half2_rn(b.x, b.y);
        *(__half2*)&o.w = __floats2half2_rn(b.z, b.w);
        dst[i] = o;
    }
}

// all four weight matrices in one launch (4 * DM*DM/8 = 524288 uint4s)
__global__ void __launch_bounds__(256) cvt_w4(
    const float4* __restrict__ s0, const float4* __restrict__ s1,
    const float4* __restrict__ s2, const float4* __restrict__ s3,
    uint4* __restrict__ dW, uint4* __restrict__ dWo) {
    int i = blockIdx.x * 256 + threadIdx.x;
    const int seg = i >> 17;            // DM*DM/8 = 131072 per segment
    const int j = i & 131071;
    const float4* s = (seg == 0) ? s0 : (seg == 1) ? s1 : (seg == 2) ? s2 : s3;
    uint4* d = (seg < 3) ? (dW + (size_t)seg * 131072 + j) : (dWo + j);
    float4 a = s[2 * j], b = s[2 * j + 1];
    uint4 o;
    *(__half2*)&o.x = __floats2half2_rn(a.x, a.y);
    *(__half2*)&o.y = __floats2half2_rn(a.z, a.w);
    *(__half2*)&o.z = __floats2half2_rn(b.x, b.y);
    *(__half2*)&o.w = __floats2half2_rn(b.z, b.w);
    *d = o;
}

// ---------------------------------------------------------------------------
// fp16 GEMM (unchanged from R9): tile 128x128, BK=64, XOR swizzle, 4 warps
// 64x64 warp tiles, 3-stage cp.async, reg double-buffered fragments, 2 CTA/SM.
// ---------------------------------------------------------------------------
#define AB_BYTES 16384
#define STAGE_BYTES (2 * AB_BYTES)
#define NST 3
#define GSMEM (NST * STAGE_BYTES)

template <int MODE>
__global__ void __launch_bounds__(128, 2) gemm_h(const float* __restrict__ bias,
                                                 float* __restrict__ Cout) {
    extern __shared__ uint8_t sm_raw[];
    const uint32_t sb = smem_u32(sm_raw);
    const int tid = threadIdx.x;
    const int lane = tid & 31;
    const int wid = tid >> 5;
    const int wm = wid >> 1;
    const int wn = wid & 1;

    const int m0 = blockIdx.y * 128;
    const int n0 = blockIdx.x * 128;
    const __half* A = (MODE == 0) ? g_X : g_MID;
    const __half* B = (MODE == 0) ? g_W : g_Wo;
    const __half* Ag = A + (size_t)m0 * DM;
    const __half* Bg = B + (size_t)n0 * DM;

    int srow[8], ssw[8];
#pragma unroll
    for (int i = 0; i < 8; i++) {
        int id = tid + i * 128;
        int r = id >> 3, c = id & 7;
        srow[i] = r;
        ssw[i] = r * 128 + ((c ^ (r & 7)) << 4);
    }
    const int scol8 = (tid & 7) * 8;

    uint32_t aOff[4]; int aSw[4];
    const int aHi = lane >> 4;
#pragma unroll
    for (int mt = 0; mt < 4; mt++) {
        int r = wm * 64 + mt * 16 + (lane & 15);
        aOff[mt] = r * 128;
        aSw[mt] = r & 7;
    }
    uint32_t bOff[4]; int bSw[4];
    const int bHi = (lane >> 3) & 1;
#pragma unroll
    for (int np = 0; np < 4; np++) {
        int r = wn * 64 + np * 16 + ((lane >> 4) << 3) + (lane & 7);
        bOff[np] = AB_BYTES + r * 128;
        bSw[np] = r & 7;
    }

    float acc[4][8][4];
#pragma unroll
    for (int mt = 0; mt < 4; mt++)
#pragma unroll
        for (int nt = 0; nt < 8; nt++)
#pragma unroll
            for (int i = 0; i < 4; i++) acc[mt][nt][i] = 0.f;

#pragma unroll
    for (int s = 0; s < NST - 1; s++) {
        const uint32_t st = sb + s * STAGE_BYTES;
        const __half* a = Ag + s * 64;
        const __half* b = Bg + s * 64;
#pragma unroll
        for (int i = 0; i < 8; i++) {
            cpasync16(st + ssw[i], a + (size_t)srow[i] * DM + scol8);
            cpasync16(st + AB_BYTES + ssw[i], b + (size_t)srow[i] * DM + scol8);
        }
        asm volatile("cp.async.commit_group;" ::: "memory");
    }

    uint32_t af[2][4][4], bf[2][4][4];

#pragma unroll 1
    for (int ks = 0; ks < 16; ks++) {
        asm volatile("cp.async.wait_group 1;" ::: "memory");
        __syncthreads();

        const uint32_t st = sb + (ks % NST) * STAGE_BYTES;

#pragma unroll
        for (int mt = 0; mt < 4; mt++)
            ldsm4(af[0][mt], st + aOff[mt] + ((aHi ^ aSw[mt]) << 4));
#pragma unroll
        for (int np = 0; np < 4; np++)
            ldsm4(bf[0][np], st + bOff[np] + ((bHi ^ bSw[np]) << 4));

        if (ks + NST - 1 < 16) {
            const int s = ks + NST - 1;
            const uint32_t stw = sb + (s % NST) * STAGE_BYTES;
            const __half* a = Ag + s * 64;
            const __half* b = Bg + s * 64;
#pragma unroll
            for (int i = 0; i < 8; i++) {
                cpasync16(stw + ssw[i], a + (size_t)srow[i] * DM + scol8);
                cpasync16(stw + AB_BYTES + ssw[i], b + (size_t)srow[i] * DM + scol8);
            }
        }
        asm volatile("cp.async.commit_group;" ::: "memory");

#pragma unroll
        for (int kk = 0; kk < 4; kk++) {
            const int cur = kk & 1, nxt = cur ^ 1;
            if (kk < 3) {
#pragma unroll
                for (int mt = 0; mt < 4; mt++)
                    ldsm4(af[nxt][mt],
                          st + aOff[mt] + ((((kk + 1) * 2 + aHi) ^ aSw[mt]) << 4));
#pragma unroll
                for (int np = 0; np < 4; np++)
                    ldsm4(bf[nxt][np],
                          st + bOff[np] + ((((kk + 1) * 2 + bHi) ^ bSw[np]) << 4));
            }
#pragma unroll
            for (int mt = 0; mt < 4; mt++)
#pragma unroll
                for (int nt = 0; nt < 8; nt++)
                    mma_f16(acc[mt][nt], af[cur][mt], &bf[cur][nt >> 1][(nt & 1) * 2]);
        }
    }

    if (MODE == 0) {
        __half* Cb = (n0 < 1024) ? g_Q : (n0 < 2048) ? g_K : g_V;
        const int col0 = (n0 & 1023) + wn * 64;
#pragma unroll
        for (int mt = 0; mt < 4; mt++) {
            const int r = m0 + wm * 64 + mt * 16 + (lane >> 2);
#pragma unroll
            for (int nt = 0; nt < 8; nt++) {
                const int c = col0 + nt * 8 + 2 * (lane & 3);
                *(__half2*)&Cb[(size_t)r * DM + c] =
                    __floats2half2_rn(acc[mt][nt][0], acc[mt][nt][1]);
                *(__half2*)&Cb[(size_t)(r + 8) * DM + c] =
                    __floats2half2_rn(acc[mt][nt][2], acc[mt][nt][3]);
            }
        }
    } else {
        const int col0 = n0 + wn * 64;
#pragma unroll
        for (int mt = 0; mt < 4; mt++) {
            const int r = m0 + wm * 64 + mt * 16 + (lane >> 2);
#pragma unroll
            for (int nt = 0; nt < 8; nt++) {
                const int c = col0 + nt * 8 + 2 * (lane & 3);
                const float b0 = bias[c], b1 = bias[c + 1];
                *(float2*)&Cout[(size_t)r * DM + c] =
                    make_float2(acc[mt][nt][0] + b0, acc[mt][nt][1] + b1);
                *(float2*)&Cout[(size_t)(r + 8) * DM + c] =
                    make_float2(acc[mt][nt][2] + b0, acc[mt][nt][3] + b1);
            }
        }
    }
}

// ---------------------------------------------------------------------------
// Attention-over-heads on tensor cores. One warp per token p.
// S = Q·K^T (16x16x64, fp32 acc), softmax in fp32 regs (quad shfl reductions),
// P repacked in-lane to A-fragments, O = P·V via ldmatrix.trans B-fragments.
// Scatter: MID[n, i*256 + (s>>4), (s&15)*64 + d] (fp16).
// smem: fp16, 144B pitch (9 x 16B chunks, odd -> conflict-free).
// ---------------------------------------------------------------------------
#define APITCH 144
#define AMAT (16 * APITCH)     // 2304 B per 16x64 fp16 matrix

__global__ void __launch_bounds__(128) attn_k() {
    __shared__ __align__(16) uint8_t sm[4 * 3 * AMAT];   // 27648 B
    const int lane = threadIdx.x & 31;
    const int w = threadIdx.x >> 5;
    const int p = blockIdx.x * 4 + w;

    const __half* q = g_Q + (size_t)p * DM;
    const __half* k = g_K + (size_t)p * DM;
    const __half* v = g_V + (size_t)p * DM;
    uint8_t* base = sm + w * 3 * AMAT;
    const uint32_t qs = smem_u32(base);
    const uint32_t ks = qs + AMAT;
    const uint32_t vs = ks + AMAT;

    // stage Q,K,V (each 16 rows x 128B) into pitch-144 smem rows
#pragma unroll
    for (int it = 0; it < 4; it++) {
        const int id = lane + it * 32;
        const int r = id >> 3, c = id & 7;
        const int dst = r * APITCH + c * 16;
        const int src = r * 64 + c * 8;                 // halves
        *(uint4*)(base + dst) = *(const uint4*)(q + src);
        *(uint4*)(base + AMAT + dst) = *(const uint4*)(k + src);
        *(uint4*)(base + 2 * AMAT + dst) = *(const uint4*)(v + src);
    }
    __syncwarp();

    // ---- S = Q K^T : 8 MMAs ----
    const uint32_t aAddr = qs + (lane & 15) * APITCH + (lane >> 4) * 16;
    const uint32_t bAddr = ks + (((lane >> 4) << 3) + (lane & 7)) * APITCH +
                           ((lane >> 3) & 1) * 16;
    float S0[4] = {0.f, 0.f, 0.f, 0.f}, S1[4] = {0.f, 0.f, 0.f, 0.f};
#pragma unroll
    for (int kc = 0; kc < 4; kc++) {
        uint32_t aq[4], bk[4];
        ldsm4(aq, aAddr + kc * 32);
        ldsm4(bk, bAddr + kc * 32);
        mma_f16(S0, aq, bk);          // cols 0-7
        mma_f16(S1, aq, bk + 2);      // cols 8-15
    }

    // ---- softmax over the 16 cols (row r in c0/c1, row r+8 in c2/c3) ----
    float r0[4] = {S0[0] * 0.125f, S0[1] * 0.125f, S1[0] * 0.125f, S1[1] * 0.125f};
    float r1[4] = {S0[2] * 0.125f, S0[3] * 0.125f, S1[2] * 0.125f, S1[3] * 0.125f};
    float m0 = fmaxf(fmaxf(r0[0], r0[1]), fmaxf(r0[2], r0[3]));
    float m1 = fmaxf(fmaxf(r1[0], r1[1]), fmaxf(r1[2], r1[3]));
    m0 = fmaxf(m0, __shfl_xor_sync(0xffffffffu, m0, 1));
    m0 = fmaxf(m0, __shfl_xor_sync(0xffffffffu, m0, 2));
    m1 = fmaxf(m1, __shfl_xor_sync(0xffffffffu, m1, 1));
    m1 = fmaxf(m1, __shfl_xor_sync(0xffffffffu, m1, 2));
    float s0 = 0.f, s1 = 0.f;
#pragma unroll
    for (int i = 0; i < 4; i++) {
        r0[i] = __expf(r0[i] - m0); s0 += r0[i];
        r1[i] = __expf(r1[i] - m1); s1 += r1[i];
    }
    s0 += __shfl_xor_sync(0xffffffffu, s0, 1);
    s0 += __shfl_xor_sync(0xffffffffu, s0, 2);
    s1 += __shfl_xor_sync(0xffffffffu, s1, 1);
    s1 += __shfl_xor_sync(0xffffffffu, s1, 2);
    const float i0 = 1.f / s0, i1 = 1.f / s1;

    // P as A-fragment (no cross-lane movement needed)
    uint32_t pa[4];
    *(__half2*)&pa[0] = __floats2half2_rn(r0[0] * i0, r0[1] * i0);  // (r,  k0-7)
    *(__half2*)&pa[1] = __floats2half2_rn(r1[0] * i1, r1[1] * i1);  // (r+8,k0-7)
    *(__half2*)&pa[2] = __floats2half2_rn(r0[2] * i0, r0[3] * i0);  // (r,  k8-15)
    *(__half2*)&pa[3] = __floats2half2_rn(r1[2] * i1, r1[3] * i1);  // (r+8,k8-15)

    // ---- O = P V : 8 MMAs via trans ldmatrix on V ----
    const uint32_t vAddr = vs + (lane & 15) * APITCH + (lane >> 4) * 16;
    float O[8][4];
#pragma unroll
    for (int nt = 0; nt < 8; nt++)
#pragma unroll
        for (int i = 0; i < 4; i++) O[nt][i] = 0.f;
#pragma unroll
    for (int g = 0; g < 4; g++) {
        uint32_t bv[4];
        ldsm4t(bv, vAddr + g * 32);
        mma_f16(O[2 * g], pa, bv);
        mma_f16(O[2 * g + 1], pa, bv + 2);
    }

    // ---- scatter store ----
    const int n = p >> 12;
    const int s = p & 4095;
    const size_t ob = (size_t)n * SEQ * DM + (size_t)(s >> 4) * DM + (size_t)(s & 15) * 64;
    const int r = lane >> 2, t2 = 2 * (lane & 3);
    __half* o0 = g_MID + ob + (size_t)r * 256 * DM;
    __half* o1 = g_MID + ob + (size_t)(r + 8) * 256 * DM;
#pragma unroll
    for (int nt = 0; nt < 8; nt++) {
        const int c = nt * 8 + t2;
        *(__half2*)(o0 + c) = __floats2half2_rn(O[nt][0], O[nt][1]);
        *(__half2*)(o1 + c) = __floats2half2_rn(O[nt][2], O[nt][3]);
    }
}

extern "C" void kernel_launch(void* const* d_in, const int* in_sizes, int n_in,
                              void* d_out, int out_size) {
    (void)in_sizes; (void)n_in; (void)out_size;
    const float* x  = (const float*)d_in[0];
    const float* Wq = (const float*)d_in[1];
    const float* Wk = (const float*)d_in[2];
    const float* Wv = (const float*)d_in[3];
    const float* Wo = (const float*)d_in[4];
    const float* bo = (const float*)d_in[5];
    float* out = (float*)d_out;

    cudaFuncSetAttribute(gemm_h<0>, cudaFuncAttributeMaxDynamicSharedMemorySize, GSMEM);
    cudaFuncSetAttribute(gemm_h<1>, cudaFuncAttributeMaxDynamicSharedMemorySize, GSMEM);

    __half* gX; __half* gW; __half* gWo;
    cudaGetSymbolAddress((void**)&gX, g_X);
    cudaGetSymbolAddress((void**)&gW, g_W);
    cudaGetSymbolAddress((void**)&gWo, g_Wo);

    // fp32 -> fp16 converts (x + all four weights in two launches)
    cvt_h<<<MTOT * DM / 8 / 256, 256>>>((const float4*)x, (uint4*)gX, MTOT * DM / 8);
    cvt_w4<<<2048, 256>>>((const float4*)Wq, (const float4*)Wk,
                          (const float4*)Wv, (const float4*)Wo,
                          (uint4*)gW, (uint4*)gWo);

    // 1) fused QKV projection (N = 3072)
    gemm_h<0><<<dim3(24, 256), 128, GSMEM>>>(nullptr, nullptr);
    // 2) attention-over-heads + scrambled reshape (tensor-core, fp16 out)
    attn_k<<<MTOT / 4, 128>>>();
    // 3) output projection + bias (fp32 out)
    gemm_h<1><<<dim3(8, 256), 128, GSMEM>>>(bo, out);
}

// round 11
// speedup vs baseline: 1.3808x; 1.0258x over previous
#include <cuda_runtime.h>
#include <cuda_fp16.h>
#include <cstdint>

#define SEQ 4096
#define DM 1024
#define MTOT 32768

// ---- scratch (device globals: sanctioned no-alloc workaround) ----
__device__ __half g_Q[(size_t)MTOT * DM];
__device__ __half g_K[(size_t)MTOT * DM];
__device__ __half g_V[(size_t)MTOT * DM];
__device__ __half g_MID[(size_t)MTOT * DM];
__device__ __half g_X[(size_t)MTOT * DM];         // fp16 x
__device__ __half g_W[(size_t)3 * DM * DM];       // fp16 [Wq;Wk;Wv]
__device__ __half g_Wo[(size_t)DM * DM];          // fp16 Wo

// ---------------------------------------------------------------------------
// helpers
// ---------------------------------------------------------------------------
__device__ __forceinline__ uint32_t smem_u32(const void* p) {
    uint32_t a;
    asm("{ .reg .u64 t; cvta.to.shared.u64 t, %1; cvt.u32.u64 %0, t; }" : "=r"(a) : "l"(p));
    return a;
}
__device__ __forceinline__ void cpasync16(uint32_t dst, const void* src) {
    asm volatile("cp.async.cg.shared.global [%0], [%1], 16;" :: "r"(dst), "l"(src) : "memory");
}
__device__ __forceinline__ void ldsm4(uint32_t* r, uint32_t addr) {
    asm volatile("ldmatrix.sync.aligned.m8n8.x4.shared.b16 {%0,%1,%2,%3}, [%4];"
                 : "=r"(r[0]), "=r"(r[1]), "=r"(r[2]), "=r"(r[3]) : "r"(addr));
}
__device__ __forceinline__ void ldsm4t(uint32_t* r, uint32_t addr) {
    asm volatile("ldmatrix.sync.aligned.m8n8.x4.trans.shared.b16 {%0,%1,%2,%3}, [%4];"
                 : "=r"(r[0]), "=r"(r[1]), "=r"(r[2]), "=r"(r[3]) : "r"(addr));
}
__device__ __forceinline__ void mma_f16(float* c, const uint32_t* a, const uint32_t* b) {
    asm volatile(
        "mma.sync.aligned.m16n8k16.row.col.f32.f16.f16.f32 "
        "{%0,%1,%2,%3}, {%4,%5,%6,%7}, {%8,%9}, {%0,%1,%2,%3};\n"
        : "+f"(c[0]), "+f"(c[1]), "+f"(c[2]), "+f"(c[3])
        : "r"(a[0]), "r"(a[1]), "r"(a[2]), "r"(a[3]), "r"(b[0]), "r"(b[1]));
}

// ---------------------------------------------------------------------------
// fp32 -> fp16 convert: x (4194304 uint4) + Wq/Wk/Wv/Wo (524288) in ONE launch
// ---------------------------------------------------------------------------
__global__ void __launch_bounds__(256) cvt_all(
    const float4* __restrict__ x,
    const float4* __restrict__ w0, const float4* __restrict__ w1,
    const float4* __restrict__ w2, const float4* __restrict__ w3,
    uint4* __restrict__ dX, uint4* __restrict__ dW, uint4* __restrict__ dWo) {
    const int i = blockIdx.x * 256 + threadIdx.x;
    const float4* s;
    uint4* d;
    if (i < 4194304) {
        s = x + 2 * (size_t)i;
        d = dX + i;
    } else {
        const int j = i - 4194304;
        const int seg = j >> 17;               // 131072 per weight matrix
        const int t = j & 131071;
        const float4* w = (seg == 0) ? w0 : (seg == 1) ? w1 : (seg == 2) ? w2 : w3;
        s = w + 2 * (size_t)t;
        d = (seg < 3) ? (dW + (size_t)seg * 131072 + t) : (dWo + t);
    }
    float4 a = s[0], b = s[1];
    uint4 o;
    *(__half2*)&o.x = __floats2half2_rn(a.x, a.y);
    *(__half2*)&o.y = __floats2half2_rn(a.z, a.w);
    *(__half2*)&o.z = __floats2half2_rn(b.x, b.y);
    *(__half2*)&o.w = __floats2half2_rn(b.z, b.w);
    *d = o;
}

// ---------------------------------------------------------------------------
// fp16 GEMM (unchanged from R9): tile 128x128, BK=64, XOR swizzle, 4 warps
// 64x64 warp tiles, 3-stage cp.async, reg double-buffered fragments, 2 CTA/SM.
// ---------------------------------------------------------------------------
#define AB_BYTES 16384
#define STAGE_BYTES (2 * AB_BYTES)
#define NST 3
#define GSMEM (NST * STAGE_BYTES)

template <int MODE>
__global__ void __launch_bounds__(128, 2) gemm_h(const float* __restrict__ bias,
                                                 float* __restrict__ Cout) {
    extern __shared__ uint8_t sm_raw[];
    const uint32_t sb = smem_u32(sm_raw);
    const int tid = threadIdx.x;
    const int lane = tid & 31;
    const int wid = tid >> 5;
    const int wm = wid >> 1;
    const int wn = wid & 1;

    const int m0 = blockIdx.y * 128;
    const int n0 = blockIdx.x * 128;
    const __half* A = (MODE == 0) ? g_X : g_MID;
    const __half* B = (MODE == 0) ? g_W : g_Wo;
    const __half* Ag = A + (size_t)m0 * DM;
    const __half* Bg = B + (size_t)n0 * DM;

    int srow[8], ssw[8];
#pragma unroll
    for (int i = 0; i < 8; i++) {
        int id = tid + i * 128;
        int r = id >> 3, c = id & 7;
        srow[i] = r;
        ssw[i] = r * 128 + ((c ^ (r & 7)) << 4);
    }
    const int scol8 = (tid & 7) * 8;

    uint32_t aOff[4]; int aSw[4];
    const int aHi = lane >> 4;
#pragma unroll
    for (int mt = 0; mt < 4; mt++) {
        int r = wm * 64 + mt * 16 + (lane & 15);
        aOff[mt] = r * 128;
        aSw[mt] = r & 7;
    }
    uint32_t bOff[4]; int bSw[4];
    const int bHi = (lane >> 3) & 1;
#pragma unroll
    for (int np = 0; np < 4; np++) {
        int r = wn * 64 + np * 16 + ((lane >> 4) << 3) + (lane & 7);
        bOff[np] = AB_BYTES + r * 128;
        bSw[np] = r & 7;
    }

    float acc[4][8][4];
#pragma unroll
    for (int mt = 0; mt < 4; mt++)
#pragma unroll
        for (int nt = 0; nt < 8; nt++)
#pragma unroll
            for (int i = 0; i < 4; i++) acc[mt][nt][i] = 0.f;

#pragma unroll
    for (int s = 0; s < NST - 1; s++) {
        const uint32_t st = sb + s * STAGE_BYTES;
        const __half* a = Ag + s * 64;
        const __half* b = Bg + s * 64;
#pragma unroll
        for (int i = 0; i < 8; i++) {
            cpasync16(st + ssw[i], a + (size_t)srow[i] * DM + scol8);
            cpasync16(st + AB_BYTES + ssw[i], b + (size_t)srow[i] * DM + scol8);
        }
        asm volatile("cp.async.commit_group;" ::: "memory");
    }

    uint32_t af[2][4][4], bf[2][4][4];

#pragma unroll 1
    for (int ks = 0; ks < 16; ks++) {
        asm volatile("cp.async.wait_group 1;" ::: "memory");
        __syncthreads();

        const uint32_t st = sb + (ks % NST) * STAGE_BYTES;

#pragma unroll
        for (int mt = 0; mt < 4; mt++)
            ldsm4(af[0][mt], st + aOff[mt] + ((aHi ^ aSw[mt]) << 4));
#pragma unroll
        for (int np = 0; np < 4; np++)
            ldsm4(bf[0][np], st + bOff[np] + ((bHi ^ bSw[np]) << 4));

        if (ks + NST - 1 < 16) {
            const int s = ks + NST - 1;
            const uint32_t stw = sb + (s % NST) * STAGE_BYTES;
            const __half* a = Ag + s * 64;
            const __half* b = Bg + s * 64;
#pragma unroll
            for (int i = 0; i < 8; i++) {
                cpasync16(stw + ssw[i], a + (size_t)srow[i] * DM + scol8);
                cpasync16(stw + AB_BYTES + ssw[i], b + (size_t)srow[i] * DM + scol8);
            }
        }
        asm volatile("cp.async.commit_group;" ::: "memory");

#pragma unroll
        for (int kk = 0; kk < 4; kk++) {
            const int cur = kk & 1, nxt = cur ^ 1;
            if (kk < 3) {
#pragma unroll
                for (int mt = 0; mt < 4; mt++)
                    ldsm4(af[nxt][mt],
                          st + aOff[mt] + ((((kk + 1) * 2 + aHi) ^ aSw[mt]) << 4));
#pragma unroll
                for (int np = 0; np < 4; np++)
                    ldsm4(bf[nxt][np],
                          st + bOff[np] + ((((kk + 1) * 2 + bHi) ^ bSw[np]) << 4));
            }
#pragma unroll
            for (int mt = 0; mt < 4; mt++)
#pragma unroll
                for (int nt = 0; nt < 8; nt++)
                    mma_f16(acc[mt][nt], af[cur][mt], &bf[cur][nt >> 1][(nt & 1) * 2]);
        }
    }

    if (MODE == 0) {
        __half* Cb = (n0 < 1024) ? g_Q : (n0 < 2048) ? g_K : g_V;
        const int col0 = (n0 & 1023) + wn * 64;
#pragma unroll
        for (int mt = 0; mt < 4; mt++) {
            const int r = m0 + wm * 64 + mt * 16 + (lane >> 2);
#pragma unroll
            for (int nt = 0; nt < 8; nt++) {
                const int c = col0 + nt * 8 + 2 * (lane & 3);
                *(__half2*)&Cb[(size_t)r * DM + c] =
                    __floats2half2_rn(acc[mt][nt][0], acc[mt][nt][1]);
                *(__half2*)&Cb[(size_t)(r + 8) * DM + c] =
                    __floats2half2_rn(acc[mt][nt][2], acc[mt][nt][3]);
            }
        }
    } else {
        const int col0 = n0 + wn * 64;
#pragma unroll
        for (int mt = 0; mt < 4; mt++) {
            const int r = m0 + wm * 64 + mt * 16 + (lane >> 2);
#pragma unroll
            for (int nt = 0; nt < 8; nt++) {
                const int c = col0 + nt * 8 + 2 * (lane & 3);
                const float b0 = bias[c], b1 = bias[c + 1];
                *(float2*)&Cout[(size_t)r * DM + c] =
                    make_float2(acc[mt][nt][0] + b0, acc[mt][nt][1] + b1);
                *(float2*)&Cout[(size_t)(r + 8) * DM + c] =
                    make_float2(acc[mt][nt][2] + b0, acc[mt][nt][3] + b1);
            }
        }
    }
}

// ---------------------------------------------------------------------------
// Attention-over-heads on tensor cores. One warp per token p.
// Staging via cp.async (gmem -> smem direct, no RF round trip): removes
// 12 LDG.128 + 12 STS.128 per thread -> halves L1 wavefront traffic.
// S = Q·K^T (fp32 acc), softmax in fp32 regs, P->A-frag in-lane,
// O = P·V via ldmatrix.trans. Scatter: MID[n, i*256+(s>>4), (s&15)*64+d].
// ---------------------------------------------------------------------------
#define APITCH 144
#define AMAT (16 * APITCH)     // 2304 B per 16x64 fp16 matrix

__global__ void __launch_bounds__(128) attn_k() {
    __shared__ __align__(16) uint8_t sm[4 * 3 * AMAT];   // 27648 B
    const int lane = threadIdx.x & 31;
    const int w = threadIdx.x >> 5;
    const int p = blockIdx.x * 4 + w;

    const __half* q = g_Q + (size_t)p * DM;
    const __half* k = g_K + (size_t)p * DM;
    const __half* v = g_V + (size_t)p * DM;
    uint8_t* base = sm + w * 3 * AMAT;
    const uint32_t qs = smem_u32(base);
    const uint32_t ks = qs + AMAT;
    const uint32_t vs = ks + AMAT;

    // stage Q,K,V (16 rows x 128B each) into pitch-144 smem via cp.async
#pragma unroll
    for (int it = 0; it < 4; it++) {
        const int id = lane + it * 32;
        const int r = id >> 3, c = id & 7;
        const int dst = r * APITCH + c * 16;
        const int src = r * 64 + c * 8;                 // halves
        cpasync16(qs + dst, q + src);
        cpasync16(ks + dst, k + src);
        cpasync16(vs + dst, v + src);
    }
    asm volatile("cp.async.commit_group;" ::: "memory");
    asm volatile("cp.async.wait_group 0;" ::: "memory");
    __syncwarp();

    // ---- S = Q K^T : 8 MMAs ----
    const uint32_t aAddr = qs + (lane & 15) * APITCH + (lane >> 4) * 16;
    const uint32_t bAddr = ks + (((lane >> 4) << 3) + (lane & 7)) * APITCH +
                           ((lane >> 3) & 1) * 16;
    float S0[4] = {0.f, 0.f, 0.f, 0.f}, S1[4] = {0.f, 0.f, 0.f, 0.f};
#pragma unroll
    for (int kc = 0; kc < 4; kc++) {
        uint32_t aq[4], bk[4];
        ldsm4(aq, aAddr + kc * 32);
        ldsm4(bk, bAddr + kc * 32);
        mma_f16(S0, aq, bk);          // cols 0-7
        mma_f16(S1, aq, bk + 2);      // cols 8-15
    }

    // ---- softmax over the 16 cols (row r in c0/c1, row r+8 in c2/c3) ----
    float r0[4] = {S0[0] * 0.125f, S0[1] * 0.125f, S1[0] * 0.125f, S1[1] * 0.125f};
    float r1[4] = {S0[2] * 0.125f, S0[3] * 0.125f, S1[2] * 0.125f, S1[3] * 0.125f};
    float m0 = fmaxf(fmaxf(r0[0], r0[1]), fmaxf(r0[2], r0[3]));
    float m1 = fmaxf(fmaxf(r1[0], r1[1]), fmaxf(r1[2], r1[3]));
    m0 = fmaxf(m0, __shfl_xor_sync(0xffffffffu, m0, 1));
    m0 = fmaxf(m0, __shfl_xor_sync(0xffffffffu, m0, 2));
    m1 = fmaxf(m1, __shfl_xor_sync(0xffffffffu, m1, 1));
    m1 = fmaxf(m1, __shfl_xor_sync(0xffffffffu, m1, 2));
    float s0 = 0.f, s1 = 0.f;
#pragma unroll
    for (int i = 0; i < 4; i++) {
        r0[i] = __expf(r0[i] - m0); s0 += r0[i];
        r1[i] = __expf(r1[i] - m1); s1 += r1[i];
    }
    s0 += __shfl_xor_sync(0xffffffffu, s0, 1);
    s0 += __shfl_xor_sync(0xffffffffu, s0, 2);
    s1 += __shfl_xor_sync(0xffffffffu, s1, 1);
    s1 += __shfl_xor_sync(0xffffffffu, s1, 2);
    const float i0 = 1.f / s0, i1 = 1.f / s1;

    // P as A-fragment (no cross-lane movement needed)
    uint32_t pa[4];
    *(__half2*)&pa[0] = __floats2half2_rn(r0[0] * i0, r0[1] * i0);  // (r,  k0-7)
    *(__half2*)&pa[1] = __floats2half2_rn(r1[0] * i1, r1[1] * i1);  // (r+8,k0-7)
    *(__half2*)&pa[2] = __floats2half2_rn(r0[2] * i0, r0[3] * i0);  // (r,  k8-15)
    *(__half2*)&pa[3] = __floats2half2_rn(r1[2] * i1, r1[3] * i1);  // (r+8,k8-15)

    // ---- O = P V : 8 MMAs via trans ldmatrix on V ----
    const uint32_t vAddr = vs + (lane & 15) * APITCH + (lane >> 4) * 16;
    float O[8][4];
#pragma unroll
    for (int nt = 0; nt < 8; nt++)
#pragma unroll
        for (int i = 0; i < 4; i++) O[nt][i] = 0.f;
#pragma unroll
    for (int g = 0; g < 4; g++) {
        uint32_t bv[4];
        ldsm4t(bv, vAddr + g * 32);
        mma_f16(O[2 * g], pa, bv);
        mma_f16(O[2 * g + 1], pa, bv + 2);
    }

    // ---- scatter store ----
    const int n = p >> 12;
    const int s = p & 4095;
    const size_t ob = (size_t)n * SEQ * DM + (size_t)(s >> 4) * DM + (size_t)(s & 15) * 64;
    const int r = lane >> 2, t2 = 2 * (lane & 3);
    __half* o0 = g_MID + ob + (size_t)r * 256 * DM;
    __half* o1 = g_MID + ob + (size_t)(r + 8) * 256 * DM;
#pragma unroll
    for (int nt = 0; nt < 8; nt++) {
        const int c = nt * 8 + t2;
        *(__half2*)(o0 + c) = __floats2half2_rn(O[nt][0], O[nt][1]);
        *(__half2*)(o1 + c) = __floats2half2_rn(O[nt][2], O[nt][3]);
    }
}

extern "C" void kernel_launch(void* const* d_in, const int* in_sizes, int n_in,
                              void* d_out, int out_size) {
    (void)in_sizes; (void)n_in; (void)out_size;
    const float* x  = (const float*)d_in[0];
    const float* Wq = (const float*)d_in[1];
    const float* Wk = (const float*)d_in[2];
    const float* Wv = (const float*)d_in[3];
    const float* Wo = (const float*)d_in[4];
    const float* bo = (const float*)d_in[5];
    float* out = (float*)d_out;

    cudaFuncSetAttribute(gemm_h<0>, cudaFuncAttributeMaxDynamicSharedMemorySize, GSMEM);
    cudaFuncSetAttribute(gemm_h<1>, cudaFuncAttributeMaxDynamicSharedMemorySize, GSMEM);

    __half* gX; __half* gW; __half* gWo;
    cudaGetSymbolAddress((void**)&gX, g_X);
    cudaGetSymbolAddress((void**)&gW, g_W);
    cudaGetSymbolAddress((void**)&gWo, g_Wo);

    // fp32 -> fp16 converts (x + all four weights, one launch)
    cvt_all<<<(4194304 + 524288) / 256, 256>>>(
        (const float4*)x, (const float4*)Wq, (const float4*)Wk,
        (const float4*)Wv, (const float4*)Wo,
        (uint4*)gX, (uint4*)gW, (uint4*)gWo);

    // 1) fused QKV projection (N = 3072)
    gemm_h<0><<<dim3(24, 256), 128, GSMEM>>>(nullptr, nullptr);
    // 2) attention-over-heads + scrambled reshape (tensor-core, fp16 out)
    attn_k<<<MTOT / 4, 128>>>();
    // 3) output projection + bias (fp32 out)
    gemm_h<1><<<dim3(8, 256), 128, GSMEM>>>(bo, out);
}

// round 12
// speedup vs baseline: 1.4035x; 1.0164x over previous
#include <cuda_runtime.h>
#include <cuda_fp16.h>
#include <cstdint>

#define SEQ 4096
#define DM 1024
#define MTOT 32768

// ---- scratch (device globals: sanctioned no-alloc workaround) ----
__device__ __half g_Q[(size_t)MTOT * DM];
__device__ __half g_K[(size_t)MTOT * DM];
__device__ __half g_V[(size_t)MTOT * DM];
__device__ __half g_MID[(size_t)MTOT * DM];
__device__ __half g_X[(size_t)MTOT * DM];         // fp16 x
__device__ __half g_W[(size_t)3 * DM * DM];       // fp16 [Wq;Wk;Wv]
__device__ __half g_Wo[(size_t)DM * DM];          // fp16 Wo

// ---------------------------------------------------------------------------
// helpers
// ---------------------------------------------------------------------------
__device__ __forceinline__ uint32_t smem_u32(const void* p) {
    uint32_t a;
    asm("{ .reg .u64 t; cvta.to.shared.u64 t, %1; cvt.u32.u64 %0, t; }" : "=r"(a) : "l"(p));
    return a;
}
__device__ __forceinline__ void cpasync16(uint32_t dst, const void* src) {
    asm volatile("cp.async.cg.shared.global [%0], [%1], 16;" :: "r"(dst), "l"(src) : "memory");
}
__device__ __forceinline__ void ldsm4(uint32_t* r, uint32_t addr) {
    asm volatile("ldmatrix.sync.aligned.m8n8.x4.shared.b16 {%0,%1,%2,%3}, [%4];"
                 : "=r"(r[0]), "=r"(r[1]), "=r"(r[2]), "=r"(r[3]) : "r"(addr));
}
__device__ __forceinline__ void ldsm4t(uint32_t* r, uint32_t addr) {
    asm volatile("ldmatrix.sync.aligned.m8n8.x4.trans.shared.b16 {%0,%1,%2,%3}, [%4];"
                 : "=r"(r[0]), "=r"(r[1]), "=r"(r[2]), "=r"(r[3]) : "r"(addr));
}
__device__ __forceinline__ void mma_f16(float* c, const uint32_t* a, const uint32_t* b) {
    asm volatile(
        "mma.sync.aligned.m16n8k16.row.col.f32.f16.f16.f32 "
        "{%0,%1,%2,%3}, {%4,%5,%6,%7}, {%8,%9}, {%0,%1,%2,%3};\n"
        : "+f"(c[0]), "+f"(c[1]), "+f"(c[2]), "+f"(c[3])
        : "r"(a[0]), "r"(a[1]), "r"(a[2]), "r"(a[3]), "r"(b[0]), "r"(b[1]));
}

// ---------------------------------------------------------------------------
// fp32 -> fp16 convert: x (4194304 uint4) + Wq/Wk/Wv/Wo (524288) in ONE launch
// ---------------------------------------------------------------------------
__global__ void __launch_bounds__(256) cvt_all(
    const float4* __restrict__ x,
    const float4* __restrict__ w0, const float4* __restrict__ w1,
    const float4* __restrict__ w2, const float4* __restrict__ w3,
    uint4* __restrict__ dX, uint4* __restrict__ dW, uint4* __restrict__ dWo) {
    const int i = blockIdx.x * 256 + threadIdx.x;
    const float4* s;
    uint4* d;
    if (i < 4194304) {
        s = x + 2 * (size_t)i;
        d = dX + i;
    } else {
        const int j = i - 4194304;
        const int seg = j >> 17;               // 131072 per weight matrix
        const int t = j & 131071;
        const float4* w = (seg == 0) ? w0 : (seg == 1) ? w1 : (seg == 2) ? w2 : w3;
        s = w + 2 * (size_t)t;
        d = (seg < 3) ? (dW + (size_t)seg * 131072 + t) : (dWo + t);
    }
    float4 a = s[0], b = s[1];
    uint4 o;
    *(__half2*)&o.x = __floats2half2_rn(a.x, a.y);
    *(__half2*)&o.y = __floats2half2_rn(a.z, a.w);
    *(__half2*)&o.z = __floats2half2_rn(b.x, b.y);
    *(__half2*)&o.w = __floats2half2_rn(b.z, b.w);
    *d = o;
}

// ---------------------------------------------------------------------------
// fp16 GEMM: tile 128x128, BK=64, XOR swizzle, 4 warps, 64x64 warp tiles,
// 3-stage cp.async, reg double-buffered fragments, 2 CTA/SM.
// NEW: epilogue repacks acc through smem (conflict-free pitches) and stores
// with coalesced STG.128 (4 full 128B lines per warp-instruction) instead of
// 64 scattered STG.32 per thread.
// ---------------------------------------------------------------------------
#define AB_BYTES 16384
#define STAGE_BYTES (2 * AB_BYTES)
#define NST 3
#define GSMEM (NST * STAGE_BYTES)
#define EPI_PITCH_H 144            // fp16 row pitch (bank-conflict-free)
#define EPI_PITCH_F 288            // fp32 row pitch

template <int MODE>
__global__ void __launch_bounds__(128, 2) gemm_h(const float* __restrict__ bias,
                                                 float* __restrict__ Cout) {
    extern __shared__ uint8_t sm_raw[];
    const uint32_t sb = smem_u32(sm_raw);
    const int tid = threadIdx.x;
    const int lane = tid & 31;
    const int wid = tid >> 5;
    const int wm = wid >> 1;
    const int wn = wid & 1;

    const int m0 = blockIdx.y * 128;
    const int n0 = blockIdx.x * 128;
    const __half* A = (MODE == 0) ? g_X : g_MID;
    const __half* B = (MODE == 0) ? g_W : g_Wo;
    const __half* Ag = A + (size_t)m0 * DM;
    const __half* Bg = B + (size_t)n0 * DM;

    int srow[8], ssw[8];
#pragma unroll
    for (int i = 0; i < 8; i++) {
        int id = tid + i * 128;
        int r = id >> 3, c = id & 7;
        srow[i] = r;
        ssw[i] = r * 128 + ((c ^ (r & 7)) << 4);
    }
    const int scol8 = (tid & 7) * 8;

    uint32_t aOff[4]; int aSw[4];
    const int aHi = lane >> 4;
#pragma unroll
    for (int mt = 0; mt < 4; mt++) {
        int r = wm * 64 + mt * 16 + (lane & 15);
        aOff[mt] = r * 128;
        aSw[mt] = r & 7;
    }
    uint32_t bOff[4]; int bSw[4];
    const int bHi = (lane >> 3) & 1;
#pragma unroll
    for (int np = 0; np < 4; np++) {
        int r = wn * 64 + np * 16 + ((lane >> 4) << 3) + (lane & 7);
        bOff[np] = AB_BYTES + r * 128;
        bSw[np] = r & 7;
    }

    float acc[4][8][4];
#pragma unroll
    for (int mt = 0; mt < 4; mt++)
#pragma unroll
        for (int nt = 0; nt < 8; nt++)
#pragma unroll
            for (int i = 0; i < 4; i++) acc[mt][nt][i] = 0.f;

#pragma unroll
    for (int s = 0; s < NST - 1; s++) {
        const uint32_t st = sb + s * STAGE_BYTES;
        const __half* a = Ag + s * 64;
        const __half* b = Bg + s * 64;
#pragma unroll
        for (int i = 0; i < 8; i++) {
            cpasync16(st + ssw[i], a + (size_t)srow[i] * DM + scol8);
            cpasync16(st + AB_BYTES + ssw[i], b + (size_t)srow[i] * DM + scol8);
        }
        asm volatile("cp.async.commit_group;" ::: "memory");
    }

    uint32_t af[2][4][4], bf[2][4][4];

#pragma unroll 1
    for (int ks = 0; ks < 16; ks++) {
        asm volatile("cp.async.wait_group 1;" ::: "memory");
        __syncthreads();

        const uint32_t st = sb + (ks % NST) * STAGE_BYTES;

#pragma unroll
        for (int mt = 0; mt < 4; mt++)
            ldsm4(af[0][mt], st + aOff[mt] + ((aHi ^ aSw[mt]) << 4));
#pragma unroll
        for (int np = 0; np < 4; np++)
            ldsm4(bf[0][np], st + bOff[np] + ((bHi ^ bSw[np]) << 4));

        if (ks + NST - 1 < 16) {
            const int s = ks + NST - 1;
            const uint32_t stw = sb + (s % NST) * STAGE_BYTES;
            const __half* a = Ag + s * 64;
            const __half* b = Bg + s * 64;
#pragma unroll
            for (int i = 0; i < 8; i++) {
                cpasync16(stw + ssw[i], a + (size_t)srow[i] * DM + scol8);
                cpasync16(stw + AB_BYTES + ssw[i], b + (size_t)srow[i] * DM + scol8);
            }
        }
        asm volatile("cp.async.commit_group;" ::: "memory");

#pragma unroll
        for (int kk = 0; kk < 4; kk++) {
            const int cur = kk & 1, nxt = cur ^ 1;
            if (kk < 3) {
#pragma unroll
                for (int mt = 0; mt < 4; mt++)
                    ldsm4(af[nxt][mt],
                          st + aOff[mt] + ((((kk + 1) * 2 + aHi) ^ aSw[mt]) << 4));
#pragma unroll
                for (int np = 0; np < 4; np++)
                    ldsm4(bf[nxt][np],
                          st + bOff[np] + ((((kk + 1) * 2 + bHi) ^ bSw[np]) << 4));
            }
#pragma unroll
            for (int mt = 0; mt < 4; mt++)
#pragma unroll
                for (int nt = 0; nt < 8; nt++)
                    mma_f16(acc[mt][nt], af[cur][mt], &bf[cur][nt >> 1][(nt & 1) * 2]);
        }
    }

    // drain async copies before reusing stage smem for the epilogue
    asm volatile("cp.async.wait_group 0;" ::: "memory");
    __syncthreads();

    // ---- epilogue: repack through smem, store coalesced STG.128 ----
    const int rq = lane >> 2, q2 = 2 * (lane & 3);
    if (MODE == 0) {
        __half* Cb = (n0 < 1024) ? g_Q : (n0 < 2048) ? g_K : g_V;
        const int gc0 = (n0 & 1023) + wn * 64;
        const int gr0 = m0 + wm * 64;
        const uint32_t eb = sb + wid * (64 * EPI_PITCH_H);   // 9216 B per warp
#pragma unroll
        for (int mt = 0; mt < 4; mt++) {
            const int r = mt * 16 + rq;
#pragma unroll
            for (int nt = 0; nt < 8; nt++) {
                const int cb = (nt * 8 + q2) * 2;
                *(__half2*)(sm_raw + (eb - sb) + r * EPI_PITCH_H + cb) =
                    __floats2half2_rn(acc[mt][nt][0], acc[mt][nt][1]);
                *(__half2*)(sm_raw + (eb - sb) + (r + 8) * EPI_PITCH_H + cb) =
                    __floats2half2_rn(acc[mt][nt][2], acc[mt][nt][3]);
            }
        }
        __syncwarp();
#pragma unroll
        for (int it = 0; it < 16; it++) {
            const int id = it * 32 + lane;
            const int r = id >> 3, c = id & 7;   // 64 rows x 8 chunks(16B)
            uint4 v = *(const uint4*)(sm_raw + (eb - sb) + r * EPI_PITCH_H + c * 16);
            *(uint4*)&Cb[(size_t)(gr0 + r) * DM + gc0 + c * 8] = v;
        }
    } else {
        const int gc0 = n0 + wn * 64;
        const int gr0 = m0 + wm * 64;
        const uint32_t ebo = wid * (64 * EPI_PITCH_F);       // 18432 B per warp
#pragma unroll
        for (int mt = 0; mt < 4; mt++) {
            const int r = mt * 16 + rq;
#pragma unroll
            for (int nt = 0; nt < 8; nt++) {
                const int c = nt * 8 + q2;
                const float b0 = bias[gc0 + c], b1 = bias[gc0 + c + 1];
                *(float2*)(sm_raw + ebo + r * EPI_PITCH_F + c * 4) =
                    make_float2(acc[mt][nt][0] + b0, acc[mt][nt][1] + b1);
                *(float2*)(sm_raw + ebo + (r + 8) * EPI_PITCH_F + c * 4) =
                    make_float2(acc[mt][nt][2] + b0, acc[mt][nt][3] + b1);
            }
        }
        __syncwarp();
#pragma unroll
        for (int it = 0; it < 32; it++) {
            const int id = it * 32 + lane;
            const int r = id >> 4, c = id & 15;  // 64 rows x 16 chunks(16B)
            uint4 v = *(const uint4*)(sm_raw + ebo + r * EPI_PITCH_F + c * 16);
            *(uint4*)&Cout[(size_t)(gr0 + r) * DM + gc0 + c * 4] = v;
        }
    }
}

// ---------------------------------------------------------------------------
// Attention-over-heads on tensor cores (unchanged from R11).
// ---------------------------------------------------------------------------
#define APITCH 144
#define AMAT (16 * APITCH)

__global__ void __launch_bounds__(128) attn_k() {
    __shared__ __align__(16) uint8_t sm[4 * 3 * AMAT];
    const int lane = threadIdx.x & 31;
    const int w = threadIdx.x >> 5;
    const int p = blockIdx.x * 4 + w;

    const __half* q = g_Q + (size_t)p * DM;
    const __half* k = g_K + (size_t)p * DM;
    const __half* v = g_V + (size_t)p * DM;
    uint8_t* base = sm + w * 3 * AMAT;
    const uint32_t qs = smem_u32(base);
    const uint32_t ks = qs + AMAT;
    const uint32_t vs = ks + AMAT;

#pragma unroll
    for (int it = 0; it < 4; it++) {
        const int id = lane + it * 32;
        const int r = id >> 3, c = id & 7;
        const int dst = r * APITCH + c * 16;
        const int src = r * 64 + c * 8;
        cpasync16(qs + dst, q + src);
        cpasync16(ks + dst, k + src);
        cpasync16(vs + dst, v + src);
    }
    asm volatile("cp.async.commit_group;" ::: "memory");
    asm volatile("cp.async.wait_group 0;" ::: "memory");
    __syncwarp();

    const uint32_t aAddr = qs + (lane & 15) * APITCH + (lane >> 4) * 16;
    const uint32_t bAddr = ks + (((lane >> 4) << 3) + (lane & 7)) * APITCH +
                           ((lane >> 3) & 1) * 16;
    float S0[4] = {0.f, 0.f, 0.f, 0.f}, S1[4] = {0.f, 0.f, 0.f, 0.f};
#pragma unroll
    for (int kc = 0; kc < 4; kc++) {
        uint32_t aq[4], bk[4];
        ldsm4(aq, aAddr + kc * 32);
        ldsm4(bk, bAddr + kc * 32);
        mma_f16(S0, aq, bk);
        mma_f16(S1, aq, bk + 2);
    }

    float r0[4] = {S0[0] * 0.125f, S0[1] * 0.125f, S1[0] * 0.125f, S1[1] * 0.125f};
    float r1[4] = {S0[2] * 0.125f, S0[3] * 0.125f, S1[2] * 0.125f, S1[3] * 0.125f};
    float m0 = fmaxf(fmaxf(r0[0], r0[1]), fmaxf(r0[2], r0[3]));
    float m1 = fmaxf(fmaxf(r1[0], r1[1]), fmaxf(r1[2], r1[3]));
    m0 = fmaxf(m0, __shfl_xor_sync(0xffffffffu, m0, 1));
    m0 = fmaxf(m0, __shfl_xor_sync(0xffffffffu, m0, 2));
    m1 = fmaxf(m1, __shfl_xor_sync(0xffffffffu, m1, 1));
    m1 = fmaxf(m1, __shfl_xor_sync(0xffffffffu, m1, 2));
    float s0 = 0.f, s1 = 0.f;
#pragma unroll
    for (int i = 0; i < 4; i++) {
        r0[i] = __expf(r0[i] - m0); s0 += r0[i];
        r1[i] = __expf(r1[i] - m1); s1 += r1[i];
    }
    s0 += __shfl_xor_sync(0xffffffffu, s0, 1);
    s0 += __shfl_xor_sync(0xffffffffu, s0, 2);
    s1 += __shfl_xor_sync(0xffffffffu, s1, 1);
    s1 += __shfl_xor_sync(0xffffffffu, s1, 2);
    const float i0 = 1.f / s0, i1 = 1.f / s1;

    uint32_t pa[4];
    *(__half2*)&pa[0] = __floats2half2_rn(r0[0] * i0, r0[1] * i0);
    *(__half2*)&pa[1] = __floats2half2_rn(r1[0] * i1, r1[1] * i1);
    *(__half2*)&pa[2] = __floats2half2_rn(r0[2] * i0, r0[3] * i0);
    *(__half2*)&pa[3] = __floats2half2_rn(r1[2] * i1, r1[3] * i1);

    const uint32_t vAddr = vs + (lane & 15) * APITCH + (lane >> 4) * 16;
    float O[8][4];
#pragma unroll
    for (int nt = 0; nt < 8; nt++)
#pragma unroll
        for (int i = 0; i < 4; i++) O[nt][i] = 0.f;
#pragma unroll
    for (int g = 0; g < 4; g++) {
        uint32_t bv[4];
        ldsm4t(bv, vAddr + g * 32);
        mma_f16(O[2 * g], pa, bv);
        mma_f16(O[2 * g + 1], pa, bv + 2);
    }

    const int n = p >> 12;
    const int s = p & 4095;
    const size_t ob = (size_t)n * SEQ * DM + (size_t)(s >> 4) * DM + (size_t)(s & 15) * 64;
    const int r = lane >> 2, t2 = 2 * (lane & 3);
    __half* o0 = g_MID + ob + (size_t)r * 256 * DM;
    __half* o1 = g_MID + ob + (size_t)(r + 8) * 256 * DM;
#pragma unroll
    for (int nt = 0; nt < 8; nt++) {
        const int c = nt * 8 + t2;
        *(__half2*)(o0 + c) = __floats2half2_rn(O[nt][0], O[nt][1]);
        *(__half2*)(o1 + c) = __floats2half2_rn(O[nt][2], O[nt][3]);
    }
}

extern "C" void kernel_launch(void* const* d_in, const int* in_sizes, int n_in,
                              void* d_out, int out_size) {
    (void)in_sizes; (void)n_in; (void)out_size;
    const float* x  = (const float*)d_in[0];
    const float* Wq = (const float*)d_in[1];
    const float* Wk = (const float*)d_in[2];
    const float* Wv = (const float*)d_in[3];
    const float* Wo = (const float*)d_in[4];
    const float* bo = (const float*)d_in[5];
    float* out = (float*)d_out;

    cudaFuncSetAttribute(gemm_h<0>, cudaFuncAttributeMaxDynamicSharedMemorySize, GSMEM);
    cudaFuncSetAttribute(gemm_h<1>, cudaFuncAttributeMaxDynamicSharedMemorySize, GSMEM);

    __half* gX; __half* gW; __half* gWo;
    cudaGetSymbolAddress((void**)&gX, g_X);
    cudaGetSymbolAddress((void**)&gW, g_W);
    cudaGetSymbolAddress((void**)&gWo, g_Wo);

    cvt_all<<<(4194304 + 524288) / 256, 256>>>(
        (const float4*)x, (const float4*)Wq, (const float4*)Wk,
        (const float4*)Wv, (const float4*)Wo,
        (uint4*)gX, (uint4*)gW, (uint4*)gWo);

    gemm_h<0><<<dim3(24, 256), 128, GSMEM>>>(nullptr, nullptr);
    attn_k<<<MTOT / 4, 128>>>();
    gemm_h<1><<<dim3(8, 256), 128, GSMEM>>>(bo, out);
}

// round 13
// speedup vs baseline: 1.4069x; 1.0025x over previous
#include <cuda_runtime.h>
#include <cuda_fp16.h>
#include <cstdint>

#define SEQ 4096
#define DM 1024
#define MTOT 32768

// ---- scratch (device globals: sanctioned no-alloc workaround) ----
__device__ __half g_Q[(size_t)MTOT * DM];
__device__ __half g_K[(size_t)MTOT * DM];
__device__ __half g_V[(size_t)MTOT * DM];
__device__ __half g_MID[(size_t)MTOT * DM];
__device__ __half g_X[(size_t)MTOT * DM];         // fp16 x
__device__ __half g_W[(size_t)3 * DM * DM];       // fp16 [Wq;Wk;Wv]
__device__ __half g_Wo[(size_t)DM * DM];          // fp16 Wo

// ---------------------------------------------------------------------------
// helpers
// ---------------------------------------------------------------------------
__device__ __forceinline__ uint32_t smem_u32(const void* p) {
    uint32_t a;
    asm("{ .reg .u64 t; cvta.to.shared.u64 t, %1; cvt.u32.u64 %0, t; }" : "=r"(a) : "l"(p));
    return a;
}
__device__ __forceinline__ void cpasync16(uint32_t dst, const void* src) {
    asm volatile("cp.async.cg.shared.global [%0], [%1], 16;" :: "r"(dst), "l"(src) : "memory");
}
__device__ __forceinline__ void ldsm4(uint32_t* r, uint32_t addr) {
    asm volatile("ldmatrix.sync.aligned.m8n8.x4.shared.b16 {%0,%1,%2,%3}, [%4];"
                 : "=r"(r[0]), "=r"(r[1]), "=r"(r[2]), "=r"(r[3]) : "r"(addr));
}
__device__ __forceinline__ void ldsm4t(uint32_t* r, uint32_t addr) {
    asm volatile("ldmatrix.sync.aligned.m8n8.x4.trans.shared.b16 {%0,%1,%2,%3}, [%4];"
                 : "=r"(r[0]), "=r"(r[1]), "=r"(r[2]), "=r"(r[3]) : "r"(addr));
}
__device__ __forceinline__ void mma_f16(float* c, const uint32_t* a, const uint32_t* b) {
    asm volatile(
        "mma.sync.aligned.m16n8k16.row.col.f32.f16.f16.f32 "
        "{%0,%1,%2,%3}, {%4,%5,%6,%7}, {%8,%9}, {%0,%1,%2,%3};\n"
        : "+f"(c[0]), "+f"(c[1]), "+f"(c[2]), "+f"(c[3])
        : "r"(a[0]), "r"(a[1]), "r"(a[2]), "r"(a[3]), "r"(b[0]), "r"(b[1]));
}

// ---------------------------------------------------------------------------
// fp32 -> fp16 convert, ILP-4: each thread handles 4 outputs strided by
// the grid (8 independent LDG.128 in flight -> MLP 8 instead of 2).
// Work: x (4194304 uint4) + Wq/Wk/Wv/Wo (524288) = 4718592 = 4 * 1179648.
// ---------------------------------------------------------------------------
#define CVT_TOT   4718592
#define CVT_STRIDE 1179648

__global__ void __launch_bounds__(256) cvt_all(
    const float4* __restrict__ x,
    const float4* __restrict__ w0, const float4* __restrict__ w1,
    const float4* __restrict__ w2, const float4* __restrict__ w3,
    uint4* __restrict__ dX, uint4* __restrict__ dW, uint4* __restrict__ dWo) {
    const int t0 = blockIdx.x * 256 + threadIdx.x;
    const float4* s[4];
    uint4* d[4];
#pragma unroll
    for (int u = 0; u < 4; u++) {
        const int i = t0 + u * CVT_STRIDE;
        if (i < 4194304) {
            s[u] = x + 2 * (size_t)i;
            d[u] = dX + i;
        } else {
            const int j = i - 4194304;
            const int seg = j >> 17;
            const int t = j & 131071;
            const float4* w = (seg == 0) ? w0 : (seg == 1) ? w1
                              : (seg == 2) ? w2 : w3;
            s[u] = w + 2 * (size_t)t;
            d[u] = (seg < 3) ? (dW + (size_t)seg * 131072 + t) : (dWo + t);
        }
    }
    float4 a[4], b[4];
#pragma unroll
    for (int u = 0; u < 4; u++) { a[u] = s[u][0]; b[u] = s[u][1]; }
#pragma unroll
    for (int u = 0; u < 4; u++) {
        uint4 o;
        *(__half2*)&o.x = __floats2half2_rn(a[u].x, a[u].y);
        *(__half2*)&o.y = __floats2half2_rn(a[u].z, a[u].w);
        *(__half2*)&o.z = __floats2half2_rn(b[u].x, b[u].y);
        *(__half2*)&o.w = __floats2half2_rn(b[u].z, b[u].w);
        *d[u] = o;
    }
}

// ---------------------------------------------------------------------------
// fp16 GEMM: tile 128x128, BK=64, XOR swizzle, 4 warps, 64x64 warp tiles,
// 3-stage cp.async, reg double-buffered fragments, 2 CTA/SM.
// Epilogue: MODE 0 repacks through smem -> coalesced STG.128 (measured win);
// MODE 1 stores directly (smem repack measured as a slight loss -> reverted).
// ---------------------------------------------------------------------------
#define AB_BYTES 16384
#define STAGE_BYTES (2 * AB_BYTES)
#define NST 3
#define GSMEM (NST * STAGE_BYTES)
#define EPI_PITCH_H 144            // fp16 row pitch (bank-conflict-free)

template <int MODE>
__global__ void __launch_bounds__(128, 2) gemm_h(const float* __restrict__ bias,
                                                 float* __restrict__ Cout) {
    extern __shared__ uint8_t sm_raw[];
    const uint32_t sb = smem_u32(sm_raw);
    const int tid = threadIdx.x;
    const int lane = tid & 31;
    const int wid = tid >> 5;
    const int wm = wid >> 1;
    const int wn = wid & 1;

    const int m0 = blockIdx.y * 128;
    const int n0 = blockIdx.x * 128;
    const __half* A = (MODE == 0) ? g_X : g_MID;
    const __half* B = (MODE == 0) ? g_W : g_Wo;
    const __half* Ag = A + (size_t)m0 * DM;
    const __half* Bg = B + (size_t)n0 * DM;

    int srow[8], ssw[8];
#pragma unroll
    for (int i = 0; i < 8; i++) {
        int id = tid + i * 128;
        int r = id >> 3, c = id & 7;
        srow[i] = r;
        ssw[i] = r * 128 + ((c ^ (r & 7)) << 4);
    }
    const int scol8 = (tid & 7) * 8;

    uint32_t aOff[4]; int aSw[4];
    const int aHi = lane >> 4;
#pragma unroll
    for (int mt = 0; mt < 4; mt++) {
        int r = wm * 64 + mt * 16 + (lane & 15);
        aOff[mt] = r * 128;
        aSw[mt] = r & 7;
    }
    uint32_t bOff[4]; int bSw[4];
    const int bHi = (lane >> 3) & 1;
#pragma unroll
    for (int np = 0; np < 4; np++) {
        int r = wn * 64 + np * 16 + ((lane >> 4) << 3) + (lane & 7);
        bOff[np] = AB_BYTES + r * 128;
        bSw[np] = r & 7;
    }

    float acc[4][8][4];
#pragma unroll
    for (int mt = 0; mt < 4; mt++)
#pragma unroll
        for (int nt = 0; nt < 8; nt++)
#pragma unroll
            for (int i = 0; i < 4; i++) acc[mt][nt][i] = 0.f;

#pragma unroll
    for (int s = 0; s < NST - 1; s++) {
        const uint32_t st = sb + s * STAGE_BYTES;
        const __half* a = Ag + s * 64;
        const __half* b = Bg + s * 64;
#pragma unroll
        for (int i = 0; i < 8; i++) {
            cpasync16(st + ssw[i], a + (size_t)srow[i] * DM + scol8);
            cpasync16(st + AB_BYTES + ssw[i], b + (size_t)srow[i] * DM + scol8);
        }
        asm volatile("cp.async.commit_group;" ::: "memory");
    }

    uint32_t af[2][4][4], bf[2][4][4];

#pragma unroll 1
    for (int ks = 0; ks < 16; ks++) {
        asm volatile("cp.async.wait_group 1;" ::: "memory");
        __syncthreads();

        const uint32_t st = sb + (ks % NST) * STAGE_BYTES;

#pragma unroll
        for (int mt = 0; mt < 4; mt++)
            ldsm4(af[0][mt], st + aOff[mt] + ((aHi ^ aSw[mt]) << 4));
#pragma unroll
        for (int np = 0; np < 4; np++)
            ldsm4(bf[0][np], st + bOff[np] + ((bHi ^ bSw[np]) << 4));

        if (ks + NST - 1 < 16) {
            const int s = ks + NST - 1;
            const uint32_t stw = sb + (s % NST) * STAGE_BYTES;
            const __half* a = Ag + s * 64;
            const __half* b = Bg + s * 64;
#pragma unroll
            for (int i = 0; i < 8; i++) {
                cpasync16(stw + ssw[i], a + (size_t)srow[i] * DM + scol8);
                cpasync16(stw + AB_BYTES + ssw[i], b + (size_t)srow[i] * DM + scol8);
            }
        }
        asm volatile("cp.async.commit_group;" ::: "memory");

#pragma unroll
        for (int kk = 0; kk < 4; kk++) {
            const int cur = kk & 1, nxt = cur ^ 1;
            if (kk < 3) {
#pragma unroll
                for (int mt = 0; mt < 4; mt++)
                    ldsm4(af[nxt][mt],
                          st + aOff[mt] + ((((kk + 1) * 2 + aHi) ^ aSw[mt]) << 4));
#pragma unroll
                for (int np = 0; np < 4; np++)
                    ldsm4(bf[nxt][np],
                          st + bOff[np] + ((((kk + 1) * 2 + bHi) ^ bSw[np]) << 4));
            }
#pragma unroll
            for (int mt = 0; mt < 4; mt++)
#pragma unroll
                for (int nt = 0; nt < 8; nt++)
                    mma_f16(acc[mt][nt], af[cur][mt], &bf[cur][nt >> 1][(nt & 1) * 2]);
        }
    }

    // ---- epilogue ----
    const int rq = lane >> 2, q2 = 2 * (lane & 3);
    if (MODE == 0) {
        // drain async copies before reusing stage smem
        asm volatile("cp.async.wait_group 0;" ::: "memory");
        __syncthreads();

        __half* Cb = (n0 < 1024) ? g_Q : (n0 < 2048) ? g_K : g_V;
        const int gc0 = (n0 & 1023) + wn * 64;
        const int gr0 = m0 + wm * 64;
        const uint32_t ebo = wid * (64 * EPI_PITCH_H);   // 9216 B per warp
#pragma unroll
        for (int mt = 0; mt < 4; mt++) {
            const int r = mt * 16 + rq;
#pragma unroll
            for (int nt = 0; nt < 8; nt++) {
                const int cb = (nt * 8 + q2) * 2;
                *(__half2*)(sm_raw + ebo + r * EPI_PITCH_H + cb) =
                    __floats2half2_rn(acc[mt][nt][0], acc[mt][nt][1]);
                *(__half2*)(sm_raw + ebo + (r + 8) * EPI_PITCH_H + cb) =
                    __floats2half2_rn(acc[mt][nt][2], acc[mt][nt][3]);
            }
        }
        __syncwarp();
#pragma unroll
        for (int it = 0; it < 16; it++) {
            const int id = it * 32 + lane;
            const int r = id >> 3, c = id & 7;   // 64 rows x 8 chunks(16B)
            uint4 v = *(const uint4*)(sm_raw + ebo + r * EPI_PITCH_H + c * 16);
            *(uint4*)&Cb[(size_t)(gr0 + r) * DM + gc0 + c * 8] = v;
        }
    } else {
        const int col0 = n0 + wn * 64;
#pragma unroll
        for (int mt = 0; mt < 4; mt++) {
            const int r = m0 + wm * 64 + mt * 16 + rq;
#pragma unroll
            for (int nt = 0; nt < 8; nt++) {
                const int c = col0 + nt * 8 + q2;
                const float b0 = bias[c], b1 = bias[c + 1];
                *(float2*)&Cout[(size_t)r * DM + c] =
                    make_float2(acc[mt][nt][0] + b0, acc[mt][nt][1] + b1);
                *(float2*)&Cout[(size_t)(r + 8) * DM + c] =
                    make_float2(acc[mt][nt][2] + b0, acc[mt][nt][3] + b1);
            }
        }
    }
}

// ---------------------------------------------------------------------------
// Attention-over-heads on tensor cores (unchanged from R11/R12).
// ---------------------------------------------------------------------------
#define APITCH 144
#define AMAT (16 * APITCH)

__global__ void __launch_bounds__(128) attn_k() {
    __shared__ __align__(16) uint8_t sm[4 * 3 * AMAT];
    const int lane = threadIdx.x & 31;
    const int w = threadIdx.x >> 5;
    const int p = blockIdx.x * 4 + w;

    const __half* q = g_Q + (size_t)p * DM;
    const __half* k = g_K + (size_t)p * DM;
    const __half* v = g_V + (size_t)p * DM;
    uint8_t* base = sm + w * 3 * AMAT;
    const uint32_t qs = smem_u32(base);
    const uint32_t ks = qs + AMAT;
    const uint32_t vs = ks + AMAT;

#pragma unroll
    for (int it = 0; it < 4; it++) {
        const int id = lane + it * 32;
        const int r = id >> 3, c = id & 7;
        const int dst = r * APITCH + c * 16;
        const int src = r * 64 + c * 8;
        cpasync16(qs + dst, q + src);
        cpasync16(ks + dst, k + src);
        cpasync16(vs + dst, v + src);
    }
    asm volatile("cp.async.commit_group;" ::: "memory");
    asm volatile("cp.async.wait_group 0;" ::: "memory");
    __syncwarp();

    const uint32_t aAddr = qs + (lane & 15) * APITCH + (lane >> 4) * 16;
    const uint32_t bAddr = ks + (((lane >> 4) << 3) + (lane & 7)) * APITCH +
                           ((lane >> 3) & 1) * 16;
    float S0[4] = {0.f, 0.f, 0.f, 0.f}, S1[4] = {0.f, 0.f, 0.f, 0.f};
#pragma unroll
    for (int kc = 0; kc < 4; kc++) {
        uint32_t aq[4], bk[4];
        ldsm4(aq, aAddr + kc * 32);
        ldsm4(bk, bAddr + kc * 32);
        mma_f16(S0, aq, bk);
        mma_f16(S1, aq, bk + 2);
    }

    float r0[4] = {S0[0] * 0.125f, S0[1] * 0.125f, S1[0] * 0.125f, S1[1] * 0.125f};
    float r1[4] = {S0[2] * 0.125f, S0[3] * 0.125f, S1[2] * 0.125f, S1[3] * 0.125f};
    float m0 = fmaxf(fmaxf(r0[0], r0[1]), fmaxf(r0[2], r0[3]));
    float m1 = fmaxf(fmaxf(r1[0], r1[1]), fmaxf(r1[2], r1[3]));
    m0 = fmaxf(m0, __shfl_xor_sync(0xffffffffu, m0, 1));
    m0 = fmaxf(m0, __shfl_xor_sync(0xffffffffu, m0, 2));
    m1 = fmaxf(m1, __shfl_xor_sync(0xffffffffu, m1, 1));
    m1 = fmaxf(m1, __shfl_xor_sync(0xffffffffu, m1, 2));
    float s0 = 0.f, s1 = 0.f;
#pragma unroll
    for (int i = 0; i < 4; i++) {
        r0[i] = __expf(r0[i] - m0); s0 += r0[i];
        r1[i] = __expf(r1[i] - m1); s1 += r1[i];
    }
    s0 += __shfl_xor_sync(0xffffffffu, s0, 1);
    s0 += __shfl_xor_sync(0xffffffffu, s0, 2);
    s1 += __shfl_xor_sync(0xffffffffu, s1, 1);
    s1 += __shfl_xor_sync(0xffffffffu, s1, 2);
    const float i0 = 1.f / s0, i1 = 1.f / s1;

    uint32_t pa[4];
    *(__half2*)&pa[0] = __floats2half2_rn(r0[0] * i0, r0[1] * i0);
    *(__half2*)&pa[1] = __floats2half2_rn(r1[0] * i1, r1[1] * i1);
    *(__half2*)&pa[2] = __floats2half2_rn(r0[2] * i0, r0[3] * i0);
    *(__half2*)&pa[3] = __floats2half2_rn(r1[2] * i1, r1[3] * i1);

    const uint32_t vAddr = vs + (lane & 15) * APITCH + (lane >> 4) * 16;
    float O[8][4];
#pragma unroll
    for (int nt = 0; nt < 8; nt++)
#pragma unroll
        for (int i = 0; i < 4; i++) O[nt][i] = 0.f;
#pragma unroll
    for (int g = 0; g < 4; g++) {
        uint32_t bv[4];
        ldsm4t(bv, vAddr + g * 32);
        mma_f16(O[2 * g], pa, bv);
        mma_f16(O[2 * g + 1], pa, bv + 2);
    }

    const int n = p >> 12;
    const int s = p & 4095;
    const size_t ob = (size_t)n * SEQ * DM + (size_t)(s >> 4) * DM + (size_t)(s & 15) * 64;
    const int r = lane >> 2, t2 = 2 * (lane & 3);
    __half* o0 = g_MID + ob + (size_t)r * 256 * DM;
    __half* o1 = g_MID + ob + (size_t)(r + 8) * 256 * DM;
#pragma unroll
    for (int nt = 0; nt < 8; nt++) {
        const int c = nt * 8 + t2;
        *(__half2*)(o0 + c) = __floats2half2_rn(O[nt][0], O[nt][1]);
        *(__half2*)(o1 + c) = __floats2half2_rn(O[nt][2], O[nt][3]);
    }
}

extern "C" void kernel_launch(void* const* d_in, const int* in_sizes, int n_in,
                              void* d_out, int out_size) {
    (void)in_sizes; (void)n_in; (void)out_size;
    const float* x  = (const float*)d_in[0];
    const float* Wq = (const float*)d_in[1];
    const float* Wk = (const float*)d_in[2];
    const float* Wv = (const float*)d_in[3];
    const float* Wo = (const float*)d_in[4];
    const float* bo = (const float*)d_in[5];
    float* out = (float*)d_out;

    cudaFuncSetAttribute(gemm_h<0>, cudaFuncAttributeMaxDynamicSharedMemorySize, GSMEM);
    cudaFuncSetAttribute(gemm_h<1>, cudaFuncAttributeMaxDynamicSharedMemorySize, GSMEM);

    __half* gX; __half* gW; __half* gWo;
    cudaGetSymbolAddress((void**)&gX, g_X);
    cudaGetSymbolAddress((void**)&gW, g_W);
    cudaGetSymbolAddress((void**)&gWo, g_Wo);

    cvt_all<<<CVT_STRIDE / 256, 256>>>(
        (const float4*)x, (const float4*)Wq, (const float4*)Wk,
        (const float4*)Wv, (const float4*)Wo,
        (uint4*)gX, (uint4*)gW, (uint4*)gWo);

    gemm_h<0><<<dim3(24, 256), 128, GSMEM>>>(nullptr, nullptr);
    attn_k<<<MTOT / 4, 128>>>();
    gemm_h<1><<<dim3(8, 256), 128, GSMEM>>>(bo, out);
}

// round 14
// speedup vs baseline: 1.4109x; 1.0028x over previous
#include <cuda_runtime.h>
#include <cuda_fp16.h>
#include <cstdint>

#define SEQ 4096
#define DM 1024
#define MTOT 32768

// ---- scratch (device globals: sanctioned no-alloc workaround) ----
__device__ __half g_Q[(size_t)MTOT * DM];
__device__ __half g_K[(size_t)MTOT * DM];
__device__ __half g_V[(size_t)MTOT * DM];
__device__ __half g_MID[(size_t)MTOT * DM];
__device__ __half g_X[(size_t)MTOT * DM];         // fp16 x
__device__ __half g_W[(size_t)3 * DM * DM];       // fp16 [Wq;Wk;Wv]
__device__ __half g_Wo[(size_t)DM * DM];          // fp16 Wo

// ---------------------------------------------------------------------------
// helpers
// ---------------------------------------------------------------------------
__device__ __forceinline__ uint32_t smem_u32(const void* p) {
    uint32_t a;
    asm("{ .reg .u64 t; cvta.to.shared.u64 t, %1; cvt.u32.u64 %0, t; }" : "=r"(a) : "l"(p));
    return a;
}
__device__ __forceinline__ void cpasync16(uint32_t dst, const void* src) {
    asm volatile("cp.async.cg.shared.global [%0], [%1], 16;" :: "r"(dst), "l"(src) : "memory");
}
__device__ __forceinline__ void ldsm4(uint32_t* r, uint32_t addr) {
    asm volatile("ldmatrix.sync.aligned.m8n8.x4.shared.b16 {%0,%1,%2,%3}, [%4];"
                 : "=r"(r[0]), "=r"(r[1]), "=r"(r[2]), "=r"(r[3]) : "r"(addr));
}
__device__ __forceinline__ void ldsm4t(uint32_t* r, uint32_t addr) {
    asm volatile("ldmatrix.sync.aligned.m8n8.x4.trans.shared.b16 {%0,%1,%2,%3}, [%4];"
                 : "=r"(r[0]), "=r"(r[1]), "=r"(r[2]), "=r"(r[3]) : "r"(addr));
}
__device__ __forceinline__ void mma_f16(float* c, const uint32_t* a, const uint32_t* b) {
    asm volatile(
        "mma.sync.aligned.m16n8k16.row.col.f32.f16.f16.f32 "
        "{%0,%1,%2,%3}, {%4,%5,%6,%7}, {%8,%9}, {%0,%1,%2,%3};\n"
        : "+f"(c[0]), "+f"(c[1]), "+f"(c[2]), "+f"(c[3])
        : "r"(a[0]), "r"(a[1]), "r"(a[2]), "r"(a[3]), "r"(b[0]), "r"(b[1]));
}

// ---------------------------------------------------------------------------
// fp32 -> fp16 convert, ILP-4 (unchanged)
// ---------------------------------------------------------------------------
#define CVT_STRIDE 1179648

__global__ void __launch_bounds__(256) cvt_all(
    const float4* __restrict__ x,
    const float4* __restrict__ w0, const float4* __restrict__ w1,
    const float4* __restrict__ w2, const float4* __restrict__ w3,
    uint4* __restrict__ dX, uint4* __restrict__ dW, uint4* __restrict__ dWo) {
    const int t0 = blockIdx.x * 256 + threadIdx.x;
    const float4* s[4];
    uint4* d[4];
#pragma unroll
    for (int u = 0; u < 4; u++) {
        const int i = t0 + u * CVT_STRIDE;
        if (i < 4194304) {
            s[u] = x + 2 * (size_t)i;
            d[u] = dX + i;
        } else {
            const int j = i - 4194304;
            const int seg = j >> 17;
            const int t = j & 131071;
            const float4* w = (seg == 0) ? w0 : (seg == 1) ? w1
                              : (seg == 2) ? w2 : w3;
            s[u] = w + 2 * (size_t)t;
            d[u] = (seg < 3) ? (dW + (size_t)seg * 131072 + t) : (dWo + t);
        }
    }
    float4 a[4], b[4];
#pragma unroll
    for (int u = 0; u < 4; u++) { a[u] = s[u][0]; b[u] = s[u][1]; }
#pragma unroll
    for (int u = 0; u < 4; u++) {
        uint4 o;
        *(__half2*)&o.x = __floats2half2_rn(a[u].x, a[u].y);
        *(__half2*)&o.y = __floats2half2_rn(a[u].z, a[u].w);
        *(__half2*)&o.z = __floats2half2_rn(b[u].x, b[u].y);
        *(__half2*)&o.w = __floats2half2_rn(b[u].z, b[u].w);
        *d[u] = o;
    }
}

// ---------------------------------------------------------------------------
// fp16 GEMM (unchanged from R13): tile 128x128, BK=64, XOR swizzle, 4 warps,
// 64x64 warp tiles, 3-stage cp.async, reg double-buffered frags, 2 CTA/SM.
// ---------------------------------------------------------------------------
#define AB_BYTES 16384
#define STAGE_BYTES (2 * AB_BYTES)
#define NST 3
#define GSMEM (NST * STAGE_BYTES)
#define EPI_PITCH_H 144

template <int MODE>
__global__ void __launch_bounds__(128, 2) gemm_h(const float* __restrict__ bias,
                                                 float* __restrict__ Cout) {
    extern __shared__ uint8_t sm_raw[];
    const uint32_t sb = smem_u32(sm_raw);
    const int tid = threadIdx.x;
    const int lane = tid & 31;
    const int wid = tid >> 5;
    const int wm = wid >> 1;
    const int wn = wid & 1;

    const int m0 = blockIdx.y * 128;
    const int n0 = blockIdx.x * 128;
    const __half* A = (MODE == 0) ? g_X : g_MID;
    const __half* B = (MODE == 0) ? g_W : g_Wo;
    const __half* Ag = A + (size_t)m0 * DM;
    const __half* Bg = B + (size_t)n0 * DM;

    int srow[8], ssw[8];
#pragma unroll
    for (int i = 0; i < 8; i++) {
        int id = tid + i * 128;
        int r = id >> 3, c = id & 7;
        srow[i] = r;
        ssw[i] = r * 128 + ((c ^ (r & 7)) << 4);
    }
    const int scol8 = (tid & 7) * 8;

    uint32_t aOff[4]; int aSw[4];
    const int aHi = lane >> 4;
#pragma unroll
    for (int mt = 0; mt < 4; mt++) {
        int r = wm * 64 + mt * 16 + (lane & 15);
        aOff[mt] = r * 128;
        aSw[mt] = r & 7;
    }
    uint32_t bOff[4]; int bSw[4];
    const int bHi = (lane >> 3) & 1;
#pragma unroll
    for (int np = 0; np < 4; np++) {
        int r = wn * 64 + np * 16 + ((lane >> 4) << 3) + (lane & 7);
        bOff[np] = AB_BYTES + r * 128;
        bSw[np] = r & 7;
    }

    float acc[4][8][4];
#pragma unroll
    for (int mt = 0; mt < 4; mt++)
#pragma unroll
        for (int nt = 0; nt < 8; nt++)
#pragma unroll
            for (int i = 0; i < 4; i++) acc[mt][nt][i] = 0.f;

#pragma unroll
    for (int s = 0; s < NST - 1; s++) {
        const uint32_t st = sb + s * STAGE_BYTES;
        const __half* a = Ag + s * 64;
        const __half* b = Bg + s * 64;
#pragma unroll
        for (int i = 0; i < 8; i++) {
            cpasync16(st + ssw[i], a + (size_t)srow[i] * DM + scol8);
            cpasync16(st + AB_BYTES + ssw[i], b + (size_t)srow[i] * DM + scol8);
        }
        asm volatile("cp.async.commit_group;" ::: "memory");
    }

    uint32_t af[2][4][4], bf[2][4][4];

#pragma unroll 1
    for (int ks = 0; ks < 16; ks++) {
        asm volatile("cp.async.wait_group 1;" ::: "memory");
        __syncthreads();

        const uint32_t st = sb + (ks % NST) * STAGE_BYTES;

#pragma unroll
        for (int mt = 0; mt < 4; mt++)
            ldsm4(af[0][mt], st + aOff[mt] + ((aHi ^ aSw[mt]) << 4));
#pragma unroll
        for (int np = 0; np < 4; np++)
            ldsm4(bf[0][np], st + bOff[np] + ((bHi ^ bSw[np]) << 4));

        if (ks + NST - 1 < 16) {
            const int s = ks + NST - 1;
            const uint32_t stw = sb + (s % NST) * STAGE_BYTES;
            const __half* a = Ag + s * 64;
            const __half* b = Bg + s * 64;
#pragma unroll
            for (int i = 0; i < 8; i++) {
                cpasync16(stw + ssw[i], a + (size_t)srow[i] * DM + scol8);
                cpasync16(stw + AB_BYTES + ssw[i], b + (size_t)srow[i] * DM + scol8);
            }
        }
        asm volatile("cp.async.commit_group;" ::: "memory");

#pragma unroll
        for (int kk = 0; kk < 4; kk++) {
            const int cur = kk & 1, nxt = cur ^ 1;
            if (kk < 3) {
#pragma unroll
                for (int mt = 0; mt < 4; mt++)
                    ldsm4(af[nxt][mt],
                          st + aOff[mt] + ((((kk + 1) * 2 + aHi) ^ aSw[mt]) << 4));
#pragma unroll
                for (int np = 0; np < 4; np++)
                    ldsm4(bf[nxt][np],
                          st + bOff[np] + ((((kk + 1) * 2 + bHi) ^ bSw[np]) << 4));
            }
#pragma unroll
            for (int mt = 0; mt < 4; mt++)
#pragma unroll
                for (int nt = 0; nt < 8; nt++)
                    mma_f16(acc[mt][nt], af[cur][mt], &bf[cur][nt >> 1][(nt & 1) * 2]);
        }
    }

    // ---- epilogue ----
    const int rq = lane >> 2, q2 = 2 * (lane & 3);
    if (MODE == 0) {
        asm volatile("cp.async.wait_group 0;" ::: "memory");
        __syncthreads();

        __half* Cb = (n0 < 1024) ? g_Q : (n0 < 2048) ? g_K : g_V;
        const int gc0 = (n0 & 1023) + wn * 64;
        const int gr0 = m0 + wm * 64;
        const uint32_t ebo = wid * (64 * EPI_PITCH_H);
#pragma unroll
        for (int mt = 0; mt < 4; mt++) {
            const int r = mt * 16 + rq;
#pragma unroll
            for (int nt = 0; nt < 8; nt++) {
                const int cb = (nt * 8 + q2) * 2;
                *(__half2*)(sm_raw + ebo + r * EPI_PITCH_H + cb) =
                    __floats2half2_rn(acc[mt][nt][0], acc[mt][nt][1]);
                *(__half2*)(sm_raw + ebo + (r + 8) * EPI_PITCH_H + cb) =
                    __floats2half2_rn(acc[mt][nt][2], acc[mt][nt][3]);
            }
        }
        __syncwarp();
#pragma unroll
        for (int it = 0; it < 16; it++) {
            const int id = it * 32 + lane;
            const int r = id >> 3, c = id & 7;
            uint4 v = *(const uint4*)(sm_raw + ebo + r * EPI_PITCH_H + c * 16);
            *(uint4*)&Cb[(size_t)(gr0 + r) * DM + gc0 + c * 8] = v;
        }
    } else {
        const int col0 = n0 + wn * 64;
#pragma unroll
        for (int mt = 0; mt < 4; mt++) {
            const int r = m0 + wm * 64 + mt * 16 + rq;
#pragma unroll
            for (int nt = 0; nt < 8; nt++) {
                const int c = col0 + nt * 8 + q2;
                const float b0 = bias[c], b1 = bias[c + 1];
                *(float2*)&Cout[(size_t)r * DM + c] =
                    make_float2(acc[mt][nt][0] + b0, acc[mt][nt][1] + b1);
                *(float2*)&Cout[(size_t)(r + 8) * DM + c] =
                    make_float2(acc[mt][nt][2] + b0, acc[mt][nt][3] + b1);
            }
        }
    }
}

// ---------------------------------------------------------------------------
// Attention-over-heads on tensor cores.
// R14: 2 tokens per warp software-pipelined (both token loads in flight
// before computing token 0), and the scatter store repacks O through the
// dead Q smem region -> coalesced uint4 stores (4 full 128B lines per warp
// instruction instead of 8 scattered sectors).
// ---------------------------------------------------------------------------
#define APITCH 144
#define AMAT (16 * APITCH)           // 2304 B per 16x64 fp16 matrix
#define TOKB (3 * AMAT)              // 6912 B per token (Q,K,V)
#define ATT_SMEM (4 * 2 * TOKB)      // 55296 B (4 warps x 2 tokens)

__device__ __forceinline__ void attn_token(uint8_t* tb, int p, int lane) {
    const uint32_t qs = smem_u32(tb);
    const uint32_t ks = qs + AMAT;
    const uint32_t vs = ks + AMAT;

    // ---- S = Q K^T : 8 MMAs ----
    const uint32_t aAddr = qs + (lane & 15) * APITCH + (lane >> 4) * 16;
    const uint32_t bAddr = ks + (((lane >> 4) << 3) + (lane & 7)) * APITCH +
                           ((lane >> 3) & 1) * 16;
    float S0[4] = {0.f, 0.f, 0.f, 0.f}, S1[4] = {0.f, 0.f, 0.f, 0.f};
#pragma unroll
    for (int kc = 0; kc < 4; kc++) {
        uint32_t aq[4], bk[4];
        ldsm4(aq, aAddr + kc * 32);
        ldsm4(bk, bAddr + kc * 32);
        mma_f16(S0, aq, bk);
        mma_f16(S1, aq, bk + 2);
    }

    // ---- softmax (row r in c0/c1, row r+8 in c2/c3) ----
    float r0[4] = {S0[0] * 0.125f, S0[1] * 0.125f, S1[0] * 0.125f, S1[1] * 0.125f};
    float r1[4] = {S0[2] * 0.125f, S0[3] * 0.125f, S1[2] * 0.125f, S1[3] * 0.125f};
    float m0 = fmaxf(fmaxf(r0[0], r0[1]), fmaxf(r0[2], r0[3]));
    float m1 = fmaxf(fmaxf(r1[0], r1[1]), fmaxf(r1[2], r1[3]));
    m0 = fmaxf(m0, __shfl_xor_sync(0xffffffffu, m0, 1));
    m0 = fmaxf(m0, __shfl_xor_sync(0xffffffffu, m0, 2));
    m1 = fmaxf(m1, __shfl_xor_sync(0xffffffffu, m1, 1));
    m1 = fmaxf(m1, __shfl_xor_sync(0xffffffffu, m1, 2));
    float s0 = 0.f, s1 = 0.f;
#pragma unroll
    for (int i = 0; i < 4; i++) {
        r0[i] = __expf(r0[i] - m0); s0 += r0[i];
        r1[i] = __expf(r1[i] - m1); s1 += r1[i];
    }
    s0 += __shfl_xor_sync(0xffffffffu, s0, 1);
    s0 += __shfl_xor_sync(0xffffffffu, s0, 2);
    s1 += __shfl_xor_sync(0xffffffffu, s1, 1);
    s1 += __shfl_xor_sync(0xffffffffu, s1, 2);
    const float i0 = 1.f / s0, i1 = 1.f / s1;

    uint32_t pa[4];
    *(__half2*)&pa[0] = __floats2half2_rn(r0[0] * i0, r0[1] * i0);
    *(__half2*)&pa[1] = __floats2half2_rn(r1[0] * i1, r1[1] * i1);
    *(__half2*)&pa[2] = __floats2half2_rn(r0[2] * i0, r0[3] * i0);
    *(__half2*)&pa[3] = __floats2half2_rn(r1[2] * i1, r1[3] * i1);

    // ---- O = P V : 8 MMAs via trans ldmatrix on V ----
    const uint32_t vAddr = vs + (lane & 15) * APITCH + (lane >> 4) * 16;
    float O[8][4];
#pragma unroll
    for (int nt = 0; nt < 8; nt++)
#pragma unroll
        for (int i = 0; i < 4; i++) O[nt][i] = 0.f;
#pragma unroll
    for (int g = 0; g < 4; g++) {
        uint32_t bv[4];
        ldsm4t(bv, vAddr + g * 32);
        mma_f16(O[2 * g], pa, bv);
        mma_f16(O[2 * g + 1], pa, bv + 2);
    }

    // ---- repack O into the dead Q region, then coalesced scatter ----
    const int rq = lane >> 2, q2 = 2 * (lane & 3);
    __syncwarp();   // all lanes past their Q ldsm before overwrite
#pragma unroll
    for (int nt = 0; nt < 8; nt++) {
        const int cb = (nt * 8 + q2) * 2;
        *(__half2*)(tb + rq * APITCH + cb) = __floats2half2_rn(O[nt][0], O[nt][1]);
        *(__half2*)(tb + (rq + 8) * APITCH + cb) = __floats2half2_rn(O[nt][2], O[nt][3]);
    }
    __syncwarp();

    const int n = p >> 12;
    const int s = p & 4095;
    const size_t ob = (size_t)n * SEQ * DM + (size_t)(s >> 4) * DM +
                      (size_t)(s & 15) * 64;
#pragma unroll
    for (int it = 0; it < 4; it++) {
        const int id = it * 32 + lane;
        const int r = id >> 3, c = id & 7;     // 16 rows x 8 chunks (16B)
        uint4 v = *(const uint4*)(tb + r * APITCH + c * 16);
        *(uint4*)&g_MID[ob + (size_t)r * 256 * DM + c * 8] = v;
    }
}

__global__ void __launch_bounds__(128) attn_k() {
    extern __shared__ __align__(16) uint8_t asm_raw[];
    const int lane = threadIdx.x & 31;
    const int w = threadIdx.x >> 5;
    const int p0 = blockIdx.x * 8 + w * 2;
    uint8_t* base = asm_raw + w * 2 * TOKB;

    // issue both tokens' staging loads (two commit groups)
#pragma unroll
    for (int t = 0; t < 2; t++) {
        const __half* q = g_Q + (size_t)(p0 + t) * DM;
        const __half* k = g_K + (size_t)(p0 + t) * DM;
        const __half* v = g_V + (size_t)(p0 + t) * DM;
        const uint32_t qs = smem_u32(base + t * TOKB);
#pragma unroll
        for (int it = 0; it < 4; it++) {
            const int id = lane + it * 32;
            const int r = id >> 3, c = id & 7;
            const int dst = r * APITCH + c * 16;
            const int src = r * 64 + c * 8;
            cpasync16(qs + dst, q + src);
            cpasync16(qs + AMAT + dst, k + src);
            cpasync16(qs + 2 * AMAT + dst, v + src);
        }
        asm volatile("cp.async.commit_group;" ::: "memory");
    }

    asm volatile("cp.async.wait_group 1;" ::: "memory");
    __syncwarp();
    attn_token(base, p0, lane);              // token 0 (token 1 still loading)

    asm volatile("cp.async.wait_group 0;" ::: "memory");
    __syncwarp();
    attn_token(base + TOKB, p0 + 1, lane);   // token 1
}

extern "C" void kernel_launch(void* const* d_in, const int* in_sizes, int n_in,
                              void* d_out, int out_size) {
    (void)in_sizes; (void)n_in; (void)out_size;
    const float* x  = (const float*)d_in[0];
    const float* Wq = (const float*)d_in[1];
    const float* Wk = (const float*)d_in[2];
    const float* Wv = (const float*)d_in[3];
    const float* Wo = (const float*)d_in[4];
    const float* bo = (const float*)d_in[5];
    float* out = (float*)d_out;

    cudaFuncSetAttribute(gemm_h<0>, cudaFuncAttributeMaxDynamicSharedMemorySize, GSMEM);
    cudaFuncSetAttribute(gemm_h<1>, cudaFuncAttributeMaxDynamicSharedMemorySize, GSMEM);
    cudaFuncSetAttribute(attn_k, cudaFuncAttributeMaxDynamicSharedMemorySize, ATT_SMEM);

    __half* gX; __half* gW; __half* gWo;
    cudaGetSymbolAddress((void**)&gX, g_X);
    cudaGetSymbolAddress((void**)&gW, g_W);
    cudaGetSymbolAddress((void**)&gWo, g_Wo);

    cvt_all<<<CVT_STRIDE / 256, 256>>>(
        (const float4*)x, (const float4*)Wq, (const float4*)Wk,
        (const float4*)Wv, (const float4*)Wo,
        (uint4*)gX, (uint4*)gW, (uint4*)gWo);

    gemm_h<0><<<dim3(24, 256), 128, GSMEM>>>(nullptr, nullptr);
    attn_k<<<MTOT / 8, 128, ATT_SMEM>>>();
    gemm_h<1><<<dim3(8, 256), 128, GSMEM>>>(bo, out);
}